// round 11
// baseline (speedup 1.0000x reference)
#include <cuda_runtime.h>
#include <cuda_bf16.h>
#include <cstdint>

// Problem constants
#define Bb 4
#define Ss 2048
#define Ee 2048
#define Hh 16
#define Dd 128
#define Mm (Bb * Ss)          // 8192
#define N_QKV (3 * Ee)        // 6144
#define HEAD_ELEMS ((size_t)Bb * Hh * Ss * Dd)   // 16,777,216

// ---------------------------------------------------------------------------
// Scratch (device globals; no allocation allowed)
// ---------------------------------------------------------------------------
__device__ __nv_bfloat16 g_qh[HEAD_ELEMS], g_ql[HEAD_ELEMS];     // q hi/lo (B,H,S,D), pre-scaled
__device__ __nv_bfloat16 g_kh[HEAD_ELEMS], g_kl[HEAD_ELEMS];     // k hi/lo
__device__ __nv_bfloat16 g_vh[HEAD_ELEMS], g_vl[HEAD_ELEMS];     // v hi/lo
__device__ __nv_bfloat16 g_xh[(size_t)Mm * Ee];                  // x hi
__device__ __nv_bfloat16 g_xl[(size_t)Mm * Ee];                  // x lo
__device__ __nv_bfloat16 g_wqkvh[(size_t)N_QKV * Ee];            // Wqkv^T hi  [N,K]
__device__ __nv_bfloat16 g_wqkvl[(size_t)N_QKV * Ee];            // Wqkv^T lo
__device__ __nv_bfloat16 g_wprojh[(size_t)Ee * Ee];              // Wproj^T hi [N,K]
__device__ __nv_bfloat16 g_wprojl[(size_t)Ee * Ee];              // Wproj^T lo
__device__ __nv_bfloat16 g_yh[(size_t)Mm * Ee];                  // attn out hi (B,S,E)
__device__ __nv_bfloat16 g_yl[(size_t)Mm * Ee];                  // attn out lo

// ---------------------------------------------------------------------------
// PTX helpers (sm_80-era: mma.sync / ldmatrix / cp.async — legal on sm_103 base)
// ---------------------------------------------------------------------------
__device__ __forceinline__ uint32_t smem_u32(const void* p) {
    uint32_t a;
    asm("{ .reg .u64 t; cvta.to.shared.u64 t, %1; cvt.u32.u64 %0, t; }" : "=r"(a) : "l"(p));
    return a;
}

#define LDM4(r, addr)                                                          \
    asm volatile("ldmatrix.sync.aligned.m8n8.x4.shared.b16 {%0,%1,%2,%3}, [%4];" \
                 : "=r"((r)[0]), "=r"((r)[1]), "=r"((r)[2]), "=r"((r)[3])      \
                 : "r"(addr))

#define LDM4T(r, addr)                                                         \
    asm volatile("ldmatrix.sync.aligned.m8n8.x4.trans.shared.b16 {%0,%1,%2,%3}, [%4];" \
                 : "=r"((r)[0]), "=r"((r)[1]), "=r"((r)[2]), "=r"((r)[3])      \
                 : "r"(addr))

#define MMA_BF16(d, a, b0, b1)                                                 \
    asm volatile("mma.sync.aligned.m16n8k16.row.col.f32.bf16.bf16.f32 "        \
                 "{%0,%1,%2,%3}, {%4,%5,%6,%7}, {%8,%9}, {%0,%1,%2,%3};"       \
                 : "+f"((d)[0]), "+f"((d)[1]), "+f"((d)[2]), "+f"((d)[3])      \
                 : "r"((a)[0]), "r"((a)[1]), "r"((a)[2]), "r"((a)[3]),         \
                   "r"(b0), "r"(b1))

#define CPA16(dst, src)                                                        \
    asm volatile("cp.async.cg.shared.global [%0], [%1], 16;"                   \
                 :: "r"(dst), "l"(src) : "memory")
#define CPA_COMMIT() asm volatile("cp.async.commit_group;" ::: "memory")
#define CPA_WAIT0()  asm volatile("cp.async.wait_group 0;" ::: "memory")

// pack two fp32 -> bf16x2 (lo = first elem in low half), round-to-nearest
__device__ __forceinline__ uint32_t pack_rn(float lo, float hi) {
    uint32_t r;
    asm("cvt.rn.bf16x2.f32 %0, %1, %2;" : "=r"(r) : "f"(hi), "f"(lo));
    return r;
}
__device__ __forceinline__ float bf_lo(uint32_t r) { return __uint_as_float(r << 16); }
__device__ __forceinline__ float bf_hi(uint32_t r) { return __uint_as_float(r & 0xFFFF0000u); }

// ---------------------------------------------------------------------------
// Conversion kernels
// ---------------------------------------------------------------------------
__global__ void __launch_bounds__(256)
conv_split(const float4* __restrict__ in, __nv_bfloat162* __restrict__ h,
           __nv_bfloat162* __restrict__ l, int n4)
{
    int i = blockIdx.x * 256 + threadIdx.x;
    if (i >= n4) return;
    float4 v = in[i];
    uint32_t h0 = pack_rn(v.x, v.y), h1 = pack_rn(v.z, v.w);
    uint32_t l0 = pack_rn(v.x - bf_lo(h0), v.y - bf_hi(h0));
    uint32_t l1 = pack_rn(v.z - bf_lo(h1), v.w - bf_hi(h1));
    ((uint32_t*)h)[2 * i] = h0; ((uint32_t*)h)[2 * i + 1] = h1;
    ((uint32_t*)l)[2 * i] = l0; ((uint32_t*)l)[2 * i + 1] = l1;
}

// W [K,N] fp32 -> out [N,K] bf16 hi/lo
__global__ void __launch_bounds__(256)
transpose_split(const float* __restrict__ W, __nv_bfloat16* __restrict__ th,
                __nv_bfloat16* __restrict__ tl, int K, int N)
{
    __shared__ float tile[32][33];
    const int n0 = blockIdx.x * 32, k0 = blockIdx.y * 32;
    const int tx = threadIdx.x & 31, ty = threadIdx.x >> 5;
#pragma unroll
    for (int r = ty; r < 32; r += 8)
        tile[r][tx] = W[(size_t)(k0 + r) * N + n0 + tx];
    __syncthreads();
#pragma unroll
    for (int r = ty; r < 32; r += 8) {
        float v = tile[tx][r];
        __nv_bfloat16 hv = __float2bfloat16(v);
        size_t o = (size_t)(n0 + r) * K + k0 + tx;
        th[o] = hv;
        tl[o] = __float2bfloat16(v - __bfloat162float(hv));
    }
}

// ---------------------------------------------------------------------------
// mma.sync bf16x3 GEMM: C[M,N] = A[M,K] * B^T (B stored [N,K]), fp32 accum.
// CTA tile 128x128, 8 warps (4x2), warp tile 32x64, K chunks of 64 (long MMA
// phases like the attention kernel), cp.async double-buffered smem (147KB,
// 1 CTA/SM), 144B row pitch (128B data + 16 pad, conflict-free ldmatrix).
// MODE 0: out0 = C + bias (proj).
// MODE 1: QKV epilogue — bias, RoPE, q*scale -> bf16 hi/lo; k,v -> fp32 + hi/lo
// ---------------------------------------------------------------------------
#define PITCH 144                      // bytes per 64-elem bf16 row (128B + 16B pad)
#define MAT_BYTES (128 * PITCH)        // 18432
#define STAGE_BYTES (4 * MAT_BYTES)    // Ah, Al, Bh, Bl = 73728
#define GEMM_SMEM (2 * STAGE_BYTES)    // 147456

template <int MODE>
__global__ void __launch_bounds__(256, 1)
gemm_mma(const __nv_bfloat16* __restrict__ Agh, const __nv_bfloat16* __restrict__ Agl,
         const __nv_bfloat16* __restrict__ Bgh, const __nv_bfloat16* __restrict__ Bgl,
         const float* __restrict__ bias,
         const float* __restrict__ cosT, const float* __restrict__ sinT,
         float* __restrict__ out0, float* __restrict__ out1, float* __restrict__ out2,
         __nv_bfloat16* __restrict__ qhp, __nv_bfloat16* __restrict__ qlp,
         __nv_bfloat16* __restrict__ khp, __nv_bfloat16* __restrict__ klp,
         __nv_bfloat16* __restrict__ vhp, __nv_bfloat16* __restrict__ vlp,
         int K, int N)
{
    extern __shared__ char sm[];
    const uint32_t sb = smem_u32(sm);
    const int t    = threadIdx.x;
    const int lane = t & 31;
    const int wid  = t >> 5;
    const int m0   = blockIdx.y * 128;
    const int n0   = blockIdx.x * 128;
    const int m_warp = (wid & 3) * 32;
    const int n_warp = (wid >> 2) * 64;

    float acc[2][8][4];
#pragma unroll
    for (int i = 0; i < 2; i++)
#pragma unroll
        for (int j = 0; j < 8; j++)
#pragma unroll
            for (int k = 0; k < 4; k++) acc[i][j][k] = 0.f;

    const int NCHUNK = K / 64;

    // each matrix: 128 rows x 8 quads(16B) = 1024 quads; 256 threads -> 4/thread
    auto load_chunk = [&](int c, int s) {
        const uint32_t stg = sb + s * STAGE_BYTES;
        const int k0 = c * 64;
        const __nv_bfloat16* gp[4] = {
            Agh + (size_t)m0 * K + k0, Agl + (size_t)m0 * K + k0,
            Bgh + (size_t)n0 * K + k0, Bgl + (size_t)n0 * K + k0 };
#pragma unroll
        for (int mmat = 0; mmat < 4; mmat++) {
            const uint32_t mb = stg + mmat * MAT_BYTES;
#pragma unroll
            for (int j = 0; j < 4; j++) {
                const int q = t + j * 256;
                const int r = q >> 3, cq = q & 7;
                CPA16(mb + r * PITCH + cq * 16, gp[mmat] + (size_t)r * K + cq * 8);
            }
        }
    };

    const uint32_t a_row  = m_warp + (lane & 15);
    const uint32_t a_byte = ((lane >> 4) & 1) * 16;
    const uint32_t b_row  = n_warp + ((lane >> 4) & 1) * 8 + (lane & 7);
    const uint32_t b_byte = ((lane >> 3) & 1) * 16;

    load_chunk(0, 0);
    CPA_COMMIT();
    CPA_WAIT0();
    __syncthreads();

    for (int c = 0; c < NCHUNK; c++) {
        const int s = c & 1;
        if (c + 1 < NCHUNK) { load_chunk(c + 1, s ^ 1); CPA_COMMIT(); }

        const uint32_t stg = sb + s * STAGE_BYTES;
        const uint32_t Ah = stg, Al = stg + MAT_BYTES;
        const uint32_t Bh = stg + 2 * MAT_BYTES, Bl = stg + 3 * MAT_BYTES;

#pragma unroll
        for (int ks = 0; ks < 4; ks++) {
            const uint32_t koff = ks * 32;
            uint32_t ah[2][4], al[2][4];
#pragma unroll
            for (int mt = 0; mt < 2; mt++) {
                LDM4(ah[mt], Ah + (a_row + mt * 16) * PITCH + koff + a_byte);
                LDM4(al[mt], Al + (a_row + mt * 16) * PITCH + koff + a_byte);
            }
            uint32_t bh[4][4], bl[4][4];
#pragma unroll
            for (int p = 0; p < 4; p++) {
                LDM4(bh[p], Bh + (b_row + p * 16) * PITCH + koff + b_byte);
                LDM4(bl[p], Bl + (b_row + p * 16) * PITCH + koff + b_byte);
            }
#pragma unroll
            for (int mt = 0; mt < 2; mt++)
#pragma unroll
                for (int nt = 0; nt < 8; nt++) {
                    const int p = nt >> 1, o = (nt & 1) * 2;
                    MMA_BF16(acc[mt][nt], ah[mt], bh[p][o], bh[p][o + 1]);
                    MMA_BF16(acc[mt][nt], ah[mt], bl[p][o], bl[p][o + 1]);
                    MMA_BF16(acc[mt][nt], al[mt], bh[p][o], bh[p][o + 1]);
                }
        }
        if (c + 1 < NCHUNK) CPA_WAIT0();
        __syncthreads();
    }

    // ---- epilogue ----
    const int lr = lane >> 2;
    const int lc = (lane & 3) * 2;
    const float rscale = 0.08838834764831845f;   // 1/sqrt(128)

#pragma unroll
    for (int mt = 0; mt < 2; mt++) {
#pragma unroll
        for (int nt = 0; nt < 8; nt++) {
            const int ncol = n_warp + nt * 8 + lc;
            const float b0 = bias[n0 + ncol];
            const float b1 = bias[n0 + ncol + 1];
#pragma unroll
            for (int half = 0; half < 2; half++) {
                const int m = m0 + m_warp + mt * 16 + lr + half * 8;
                float v0 = acc[mt][nt][half * 2 + 0] + b0;
                float v1 = acc[mt][nt][half * 2 + 1] + b1;
                if (MODE == 0) {
                    *(float2*)&out0[(size_t)m * N + n0 + ncol] = make_float2(v0, v1);
                } else {
                    const int part = n0 >> 11;           // 0=q, 1=k, 2=v
                    const int hh   = (n0 & 2047) >> 7;
                    const int bb   = m >> 11;
                    const int ss   = m & 2047;
                    if (part < 2) {
                        const float cs0 = cosT[ss * Dd + ncol];
                        const float sn0 = sinT[ss * Dd + ncol];
                        const float cs1 = cosT[ss * Dd + ncol + 1];
                        const float sn1 = sinT[ss * Dd + ncol + 1];
                        const float e = v0, o = v1;
                        v0 = e * cs0 - o * sn0;
                        v1 = o * cs1 + e * sn1;
                    }
                    size_t idx = ((((size_t)bb * Hh + hh) * Ss) + ss) * Dd + ncol;
                    if (part == 0) {
                        float s0 = v0 * rscale, s1 = v1 * rscale;
                        uint32_t ph = pack_rn(s0, s1);
                        uint32_t pl = pack_rn(s0 - bf_lo(ph), s1 - bf_hi(ph));
                        *(uint32_t*)(qhp + idx) = ph;
                        *(uint32_t*)(qlp + idx) = pl;
                    } else {
                        float* dst = (part == 1) ? out1 : out2;
                        *(float2*)&dst[idx] = make_float2(v0, v1);
                        __nv_bfloat16* dh = (part == 1) ? khp : vhp;
                        __nv_bfloat16* dl = (part == 1) ? klp : vlp;
                        uint32_t ph = pack_rn(v0, v1);
                        uint32_t pl = pack_rn(v0 - bf_lo(ph), v1 - bf_hi(ph));
                        *(uint32_t*)(dh + idx) = ph;
                        *(uint32_t*)(dl + idx) = pl;
                    }
                }
            }
        }
    }
}

// ---------------------------------------------------------------------------
// Tensor-core flash attention (bf16 hi/lo, 3-pass, mma.sync). Exact R6 config:
// CTA = 128 q-rows of one (b,h); 8 warps x 16 rows; BK=64; D=128.
// K/V hi/lo double-buffered in smem via cp.async; V via ldmatrix.trans.
// ---------------------------------------------------------------------------
#define AT_PITCH 272                 // 128 bf16 = 256B + 16B pad
#define AT_QBYTES (128 * AT_PITCH)   // 34816
#define AT_KBYTES (64 * AT_PITCH)    // 17408
#define AT_STAGE  (4 * AT_KBYTES)    // Kh,Kl,Vh,Vl = 69632
#define AT_SMEM   (2 * AT_QBYTES + 2 * AT_STAGE)   // 208896

__global__ void __launch_bounds__(256, 1)
mha_attn_mma(const __nv_bfloat16* __restrict__ qh, const __nv_bfloat16* __restrict__ ql,
             const __nv_bfloat16* __restrict__ kh, const __nv_bfloat16* __restrict__ kl,
             const __nv_bfloat16* __restrict__ vh, const __nv_bfloat16* __restrict__ vl,
             __nv_bfloat16* __restrict__ yh, __nv_bfloat16* __restrict__ yl)
{
    extern __shared__ char sm[];
    const uint32_t sb = smem_u32(sm);
    const int t = threadIdx.x, lane = t & 31, w = t >> 5;
    const int q0 = blockIdx.x * 128;
    const int h  = blockIdx.y, b = blockIdx.z;
    const size_t base = ((size_t)b * Hh + h) * (size_t)Ss * Dd;

    const uint32_t QH = sb, QL = sb + AT_QBYTES;
    const uint32_t ST0 = sb + 2 * AT_QBYTES;

    // ---- load Q hi/lo (128 rows x 256B each) ----
    {
        const __nv_bfloat16* sq[2] = { qh + base + (size_t)q0 * Dd,
                                       ql + base + (size_t)q0 * Dd };
#pragma unroll
        for (int mmat = 0; mmat < 2; mmat++) {
            const uint32_t dstb = mmat ? QL : QH;
#pragma unroll
            for (int j = 0; j < 8; j++) {
                int idx = t + j * 256;               // 2048 16B-chunks
                int r = idx >> 4, c = idx & 15;
                CPA16(dstb + r * AT_PITCH + c * 16, sq[mmat] + (size_t)r * Dd + c * 8);
            }
        }
    }

    auto load_kv = [&](int kt, int s) {
        const size_t off = base + (size_t)kt * 64 * Dd;
        const __nv_bfloat16* srcs[4] = { kh + off, kl + off, vh + off, vl + off };
        const uint32_t stb = ST0 + s * AT_STAGE;
#pragma unroll
        for (int mmat = 0; mmat < 4; mmat++)
#pragma unroll
            for (int j = 0; j < 4; j++) {
                int idx = t + j * 256;               // 1024 chunks per matrix
                int r = idx >> 4, c = idx & 15;
                CPA16(stb + mmat * AT_KBYTES + r * AT_PITCH + c * 16,
                      srcs[mmat] + (size_t)r * Dd + c * 8);
            }
    };

    load_kv(0, 0);
    CPA_COMMIT();
    CPA_WAIT0();
    __syncthreads();

    const int lr = lane >> 2, lcq = lane & 3;
    // ldmatrix address components
    const uint32_t qrow_off = (uint32_t)(w * 16 + (lane & 15)) * AT_PITCH + ((lane >> 4) & 1) * 16;
    const uint32_t krow_off = (uint32_t)(((lane >> 4) & 1) * 8 + (lane & 7)) * AT_PITCH + ((lane >> 3) & 1) * 16;
    const uint32_t vrow_off = (uint32_t)(lane & 15) * AT_PITCH + ((lane >> 4) & 1) * 16;

    float o[16][4];
#pragma unroll
    for (int i = 0; i < 16; i++)
#pragma unroll
        for (int j = 0; j < 4; j++) o[i][j] = 0.f;
    float mrow[2] = { -1e30f, -1e30f };
    float lrow[2] = { 0.f, 0.f };

    for (int kt = 0; kt < Ss / 64; kt++) {
        const int s = kt & 1;
        if (kt + 1 < Ss / 64) { load_kv(kt + 1, s ^ 1); CPA_COMMIT(); }

        const uint32_t KHs = ST0 + s * AT_STAGE;
        const uint32_t KLs = KHs + AT_KBYTES;
        const uint32_t VHs = KHs + 2 * AT_KBYTES;
        const uint32_t VLs = KHs + 3 * AT_KBYTES;

        // ---- S = Q K^T (hi/lo 3-pass), warp tile 16x64 ----
        float sc[8][4];
#pragma unroll
        for (int i = 0; i < 8; i++)
#pragma unroll
            for (int j = 0; j < 4; j++) sc[i][j] = 0.f;

#pragma unroll
        for (int ks = 0; ks < 8; ks++) {
            uint32_t ahf[4], alf[4];
            LDM4(ahf, QH + qrow_off + ks * 32);
            LDM4(alf, QL + qrow_off + ks * 32);
#pragma unroll
            for (int ntp = 0; ntp < 4; ntp++) {
                uint32_t bhf[4], blf[4];
                LDM4(bhf, KHs + ntp * 16 * AT_PITCH + krow_off + ks * 32);
                LDM4(blf, KLs + ntp * 16 * AT_PITCH + krow_off + ks * 32);
                MMA_BF16(sc[2 * ntp],     ahf, bhf[0], bhf[1]);
                MMA_BF16(sc[2 * ntp + 1], ahf, bhf[2], bhf[3]);
                MMA_BF16(sc[2 * ntp],     ahf, blf[0], blf[1]);
                MMA_BF16(sc[2 * ntp + 1], ahf, blf[2], blf[3]);
                MMA_BF16(sc[2 * ntp],     alf, bhf[0], bhf[1]);
                MMA_BF16(sc[2 * ntp + 1], alf, bhf[2], bhf[3]);
            }
        }

        // ---- online softmax (rows lr and lr+8; quad-local reductions) ----
#pragma unroll
        for (int r = 0; r < 2; r++) {
            float mx = -1e30f;
#pragma unroll
            for (int nt = 0; nt < 8; nt++)
                mx = fmaxf(mx, fmaxf(sc[nt][2 * r], sc[nt][2 * r + 1]));
            mx = fmaxf(mx, __shfl_xor_sync(0xffffffffu, mx, 1));
            mx = fmaxf(mx, __shfl_xor_sync(0xffffffffu, mx, 2));
            const float mn = fmaxf(mrow[r], mx);
            const float al = __expf(mrow[r] - mn);
            mrow[r] = mn;
            float rs = 0.f;
#pragma unroll
            for (int nt = 0; nt < 8; nt++) {
                float p0 = __expf(sc[nt][2 * r]     - mn);
                float p1 = __expf(sc[nt][2 * r + 1] - mn);
                sc[nt][2 * r] = p0; sc[nt][2 * r + 1] = p1;
                rs += p0 + p1;
            }
            rs += __shfl_xor_sync(0xffffffffu, rs, 1);
            rs += __shfl_xor_sync(0xffffffffu, rs, 2);
            lrow[r] = lrow[r] * al + rs;
#pragma unroll
            for (int nt = 0; nt < 16; nt++) {
                o[nt][2 * r] *= al; o[nt][2 * r + 1] *= al;
            }
        }

        // ---- O += P V (hi/lo 3-pass); P A-frags straight from sc regs ----
#pragma unroll
        for (int kg = 0; kg < 4; kg++) {
            uint32_t afh[4], afl[4];
#pragma unroll
            for (int u = 0; u < 2; u++) {          // u=0: ntile 2kg, u=1: ntile 2kg+1
                const float e0 = sc[2 * kg + u][0], e1 = sc[2 * kg + u][1];
                const float e2 = sc[2 * kg + u][2], e3 = sc[2 * kg + u][3];
                uint32_t h01 = pack_rn(e0, e1);
                uint32_t h23 = pack_rn(e2, e3);
                afh[2 * u]     = h01;
                afh[2 * u + 1] = h23;
                afl[2 * u]     = pack_rn(e0 - bf_lo(h01), e1 - bf_hi(h01));
                afl[2 * u + 1] = pack_rn(e2 - bf_lo(h23), e3 - bf_hi(h23));
            }
#pragma unroll
            for (int dg = 0; dg < 8; dg++) {
                uint32_t bh4[4], bl4[4];
                LDM4T(bh4, VHs + kg * 16 * AT_PITCH + vrow_off + dg * 32);
                LDM4T(bl4, VLs + kg * 16 * AT_PITCH + vrow_off + dg * 32);
                MMA_BF16(o[2 * dg],     afh, bh4[0], bh4[1]);
                MMA_BF16(o[2 * dg + 1], afh, bh4[2], bh4[3]);
                MMA_BF16(o[2 * dg],     afh, bl4[0], bl4[1]);
                MMA_BF16(o[2 * dg + 1], afh, bl4[2], bl4[3]);
                MMA_BF16(o[2 * dg],     afl, bh4[0], bh4[1]);
                MMA_BF16(o[2 * dg + 1], afl, bh4[2], bh4[3]);
            }
        }

        CPA_WAIT0();
        __syncthreads();
    }

    // ---- epilogue: scale by 1/l, emit bf16 hi/lo y in (B,S,E) ----
    const float inv0 = 1.f / lrow[0];
    const float inv1 = 1.f / lrow[1];
    const int row0 = q0 + w * 16 + lr;
    const int row1 = row0 + 8;
#pragma unroll
    for (int nt = 0; nt < 16; nt++) {
        const int col = h * Dd + nt * 8 + 2 * lcq;
        {
            float v0 = o[nt][0] * inv0, v1 = o[nt][1] * inv0;
            uint32_t ph = pack_rn(v0, v1);
            uint32_t pl = pack_rn(v0 - bf_lo(ph), v1 - bf_hi(ph));
            size_t idx = ((size_t)b * Ss + row0) * Ee + col;
            *(uint32_t*)(yh + idx) = ph;
            *(uint32_t*)(yl + idx) = pl;
        }
        {
            float v0 = o[nt][2] * inv1, v1 = o[nt][3] * inv1;
            uint32_t ph = pack_rn(v0, v1);
            uint32_t pl = pack_rn(v0 - bf_lo(ph), v1 - bf_hi(ph));
            size_t idx = ((size_t)b * Ss + row1) * Ee + col;
            *(uint32_t*)(yh + idx) = ph;
            *(uint32_t*)(yl + idx) = pl;
        }
    }
}

// ---------------------------------------------------------------------------
extern "C" void kernel_launch(void* const* d_in, const int* in_sizes, int n_in,
                              void* d_out, int out_size)
{
    const float* x     = (const float*)d_in[0];
    const float* cosT  = (const float*)d_in[1];
    const float* sinT  = (const float*)d_in[2];
    const float* Wqkv  = (const float*)d_in[3];
    const float* bqkv  = (const float*)d_in[4];
    const float* Wproj = (const float*)d_in[5];
    const float* bproj = (const float*)d_in[6];

    float* out  = (float*)d_out;                 // (B,S,E)
    float* kout = out + HEAD_ELEMS;              // (B,H,S,D)
    float* vout = out + 2 * HEAD_ELEMS;          // (B,H,S,D)

    __nv_bfloat16 *xh, *xl, *wqh, *wql, *wph, *wpl, *yh, *yl;
    __nv_bfloat16 *qhp, *qlp, *khp, *klp, *vhp, *vlp;
    cudaGetSymbolAddress((void**)&xh,  g_xh);
    cudaGetSymbolAddress((void**)&xl,  g_xl);
    cudaGetSymbolAddress((void**)&wqh, g_wqkvh);
    cudaGetSymbolAddress((void**)&wql, g_wqkvl);
    cudaGetSymbolAddress((void**)&wph, g_wprojh);
    cudaGetSymbolAddress((void**)&wpl, g_wprojl);
    cudaGetSymbolAddress((void**)&yh,  g_yh);
    cudaGetSymbolAddress((void**)&yl,  g_yl);
    cudaGetSymbolAddress((void**)&qhp, g_qh);
    cudaGetSymbolAddress((void**)&qlp, g_ql);
    cudaGetSymbolAddress((void**)&khp, g_kh);
    cudaGetSymbolAddress((void**)&klp, g_kl);
    cudaGetSymbolAddress((void**)&vhp, g_vh);
    cudaGetSymbolAddress((void**)&vlp, g_vl);

    // 0) conversions: x -> hi/lo, weights -> transposed hi/lo
    {
        const int n4 = (Mm * Ee) / 4;
        conv_split<<<(n4 + 255) / 256, 256>>>((const float4*)x,
                                              (__nv_bfloat162*)xh, (__nv_bfloat162*)xl, n4);
        transpose_split<<<dim3(N_QKV / 32, Ee / 32), 256>>>(Wqkv, wqh, wql, Ee, N_QKV);
        transpose_split<<<dim3(Ee / 32, Ee / 32), 256>>>(Wproj, wph, wpl, Ee, Ee);
    }

    // 1) QKV GEMM + bias + RoPE: q (scaled) -> bf16 hi/lo; k,v -> fp32 out + hi/lo
    {
        cudaFuncSetAttribute(gemm_mma<1>, cudaFuncAttributeMaxDynamicSharedMemorySize, GEMM_SMEM);
        dim3 grid(N_QKV / 128, Mm / 128);
        gemm_mma<1><<<grid, 256, GEMM_SMEM>>>(xh, xl, wqh, wql, bqkv, cosT, sinT,
                                              nullptr, kout, vout,
                                              qhp, qlp, khp, klp, vhp, vlp, Ee, N_QKV);
    }

    // 2) Tensor-core flash attention -> bf16 hi/lo y
    {
        cudaFuncSetAttribute(mha_attn_mma, cudaFuncAttributeMaxDynamicSharedMemorySize, AT_SMEM);
        dim3 grid(Ss / 128, Hh, Bb);
        mha_attn_mma<<<grid, 256, AT_SMEM>>>(qhp, qlp, khp, klp, vhp, vlp, yh, yl);
    }

    // 3) Projection GEMM + bias
    {
        cudaFuncSetAttribute(gemm_mma<0>, cudaFuncAttributeMaxDynamicSharedMemorySize, GEMM_SMEM);
        dim3 grid(Ee / 128, Mm / 128);
        gemm_mma<0><<<grid, 256, GEMM_SMEM>>>(yh, yl, wph, wpl, bproj, nullptr, nullptr,
                                              out, nullptr, nullptr,
                                              nullptr, nullptr, nullptr, nullptr,
                                              nullptr, nullptr, Ee, Ee);
    }
}

// round 12
// speedup vs baseline: 1.7389x; 1.7389x over previous
#include <cuda_runtime.h>
#include <cuda_bf16.h>
#include <cuda_fp16.h>
#include <cstdint>

// Problem constants
#define Bb 4
#define Ss 2048
#define Ee 2048
#define Hh 16
#define Dd 128
#define Mm (Bb * Ss)          // 8192
#define N_QKV (3 * Ee)        // 6144
#define HEAD_ELEMS ((size_t)Bb * Hh * Ss * Dd)   // 16,777,216

// ---------------------------------------------------------------------------
// Scratch (device globals; no allocation allowed)
// ---------------------------------------------------------------------------
__device__ __nv_bfloat16 g_qh[HEAD_ELEMS], g_ql[HEAD_ELEMS];     // q hi/lo (B,H,S,D), pre-scaled
__device__ __nv_bfloat16 g_kh[HEAD_ELEMS], g_kl[HEAD_ELEMS];     // k hi/lo
__device__ __nv_bfloat16 g_vh[HEAD_ELEMS], g_vl[HEAD_ELEMS];     // v hi/lo
__device__ __half g_xf[(size_t)Mm * Ee];                         // x fp16
__device__ __half g_wqkvf[(size_t)N_QKV * Ee];                   // Wqkv^T fp16 [N,K]
__device__ __half g_wprojf[(size_t)Ee * Ee];                     // Wproj^T fp16 [N,K]
__device__ __half g_yf[(size_t)Mm * Ee];                         // attn out fp16 (B,S,E)

// ---------------------------------------------------------------------------
// PTX helpers (sm_80-era: mma.sync / ldmatrix / cp.async — legal on sm_103 base)
// ---------------------------------------------------------------------------
__device__ __forceinline__ uint32_t smem_u32(const void* p) {
    uint32_t a;
    asm("{ .reg .u64 t; cvta.to.shared.u64 t, %1; cvt.u32.u64 %0, t; }" : "=r"(a) : "l"(p));
    return a;
}

#define LDM4(r, addr)                                                          \
    asm volatile("ldmatrix.sync.aligned.m8n8.x4.shared.b16 {%0,%1,%2,%3}, [%4];" \
                 : "=r"((r)[0]), "=r"((r)[1]), "=r"((r)[2]), "=r"((r)[3])      \
                 : "r"(addr))

#define LDM4T(r, addr)                                                         \
    asm volatile("ldmatrix.sync.aligned.m8n8.x4.trans.shared.b16 {%0,%1,%2,%3}, [%4];" \
                 : "=r"((r)[0]), "=r"((r)[1]), "=r"((r)[2]), "=r"((r)[3])      \
                 : "r"(addr))

#define MMA_BF16(d, a, b0, b1)                                                 \
    asm volatile("mma.sync.aligned.m16n8k16.row.col.f32.bf16.bf16.f32 "        \
                 "{%0,%1,%2,%3}, {%4,%5,%6,%7}, {%8,%9}, {%0,%1,%2,%3};"       \
                 : "+f"((d)[0]), "+f"((d)[1]), "+f"((d)[2]), "+f"((d)[3])      \
                 : "r"((a)[0]), "r"((a)[1]), "r"((a)[2]), "r"((a)[3]),         \
                   "r"(b0), "r"(b1))

#define MMA_F16(d, a, b0, b1)                                                  \
    asm volatile("mma.sync.aligned.m16n8k16.row.col.f32.f16.f16.f32 "          \
                 "{%0,%1,%2,%3}, {%4,%5,%6,%7}, {%8,%9}, {%0,%1,%2,%3};"       \
                 : "+f"((d)[0]), "+f"((d)[1]), "+f"((d)[2]), "+f"((d)[3])      \
                 : "r"((a)[0]), "r"((a)[1]), "r"((a)[2]), "r"((a)[3]),         \
                   "r"(b0), "r"(b1))

#define CPA16(dst, src)                                                        \
    asm volatile("cp.async.cg.shared.global [%0], [%1], 16;"                   \
                 :: "r"(dst), "l"(src) : "memory")
#define CPA_COMMIT() asm volatile("cp.async.commit_group;" ::: "memory")
#define CPA_WAIT0()  asm volatile("cp.async.wait_group 0;" ::: "memory")

// pack two fp32 -> bf16x2 (lo = first elem in low half), round-to-nearest
__device__ __forceinline__ uint32_t pack_rn(float lo, float hi) {
    uint32_t r;
    asm("cvt.rn.bf16x2.f32 %0, %1, %2;" : "=r"(r) : "f"(hi), "f"(lo));
    return r;
}
__device__ __forceinline__ float bf_lo(uint32_t r) { return __uint_as_float(r << 16); }
__device__ __forceinline__ float bf_hi(uint32_t r) { return __uint_as_float(r & 0xFFFF0000u); }

// ---------------------------------------------------------------------------
// Conversion kernels
// ---------------------------------------------------------------------------
__global__ void __launch_bounds__(256)
conv_half(const float4* __restrict__ in, __half2* __restrict__ o, int n4)
{
    int i = blockIdx.x * 256 + threadIdx.x;
    if (i >= n4) return;
    float4 v = in[i];
    o[2 * i]     = __floats2half2_rn(v.x, v.y);
    o[2 * i + 1] = __floats2half2_rn(v.z, v.w);
}

// W [K,N] fp32 -> out [N,K] fp16
__global__ void __launch_bounds__(256)
transpose_half(const float* __restrict__ W, __half* __restrict__ th, int K, int N)
{
    __shared__ float tile[32][33];
    const int n0 = blockIdx.x * 32, k0 = blockIdx.y * 32;
    const int tx = threadIdx.x & 31, ty = threadIdx.x >> 5;
#pragma unroll
    for (int r = ty; r < 32; r += 8)
        tile[r][tx] = W[(size_t)(k0 + r) * N + n0 + tx];
    __syncthreads();
#pragma unroll
    for (int r = ty; r < 32; r += 8)
        th[(size_t)(n0 + r) * K + k0 + tx] = __float2half_rn(tile[tx][r]);
}

// ---------------------------------------------------------------------------
// mma.sync fp16 single-pass GEMM: C[M,N] = A[M,K] * B^T (B stored [N,K]),
// fp32 accum. R6 tile config: CTA 128x128, 8 warps (4x2), warp tile 32x64,
// K chunks of 32, cp.async double-buffered smem (40KB -> high occupancy),
// 80B row pitch (conflict-free ldmatrix).
// MODE 0: out0 = C + bias (proj).
// MODE 1: QKV epilogue — bias, RoPE, q*scale -> bf16 hi/lo; k,v -> fp32 + hi/lo
// ---------------------------------------------------------------------------
#define PITCH 80                       // bytes per 32-elem fp16 row (64B + 16B pad)
#define MAT_BYTES (128 * PITCH)        // 10240
#define STAGE_BYTES (2 * MAT_BYTES)    // A, B = 20480
#define GEMM_SMEM (2 * STAGE_BYTES)    // 40960

template <int MODE>
__global__ void __launch_bounds__(256)
gemm_mma(const __half* __restrict__ Ag, const __half* __restrict__ Bg,
         const float* __restrict__ bias,
         const float* __restrict__ cosT, const float* __restrict__ sinT,
         float* __restrict__ out0, float* __restrict__ out1, float* __restrict__ out2,
         __nv_bfloat16* __restrict__ qhp, __nv_bfloat16* __restrict__ qlp,
         __nv_bfloat16* __restrict__ khp, __nv_bfloat16* __restrict__ klp,
         __nv_bfloat16* __restrict__ vhp, __nv_bfloat16* __restrict__ vlp,
         int K, int N)
{
    extern __shared__ char sm[];
    const uint32_t sb = smem_u32(sm);
    const int t    = threadIdx.x;
    const int lane = t & 31;
    const int wid  = t >> 5;
    const int m0   = blockIdx.y * 128;
    const int n0   = blockIdx.x * 128;
    const int m_warp = (wid & 3) * 32;
    const int n_warp = (wid >> 2) * 64;

    float acc[2][8][4];
#pragma unroll
    for (int i = 0; i < 2; i++)
#pragma unroll
        for (int j = 0; j < 8; j++)
#pragma unroll
            for (int k = 0; k < 4; k++) acc[i][j][k] = 0.f;

    const int q0i = t, q1i = t + 256;
    const int r0 = q0i >> 2, c0q = q0i & 3;
    const int r1 = q1i >> 2, c1q = q1i & 3;

    const int NCHUNK = K / 32;

    auto load_chunk = [&](int c, int s) {
        const uint32_t stg = sb + s * STAGE_BYTES;
        const int k0 = c * 32;
        const __half* gp[2] = { Ag + (size_t)m0 * K + k0, Bg + (size_t)n0 * K + k0 };
#pragma unroll
        for (int mmat = 0; mmat < 2; mmat++) {
            const uint32_t mb = stg + mmat * MAT_BYTES;
            CPA16(mb + r0 * PITCH + c0q * 16, gp[mmat] + (size_t)r0 * K + c0q * 8);
            CPA16(mb + r1 * PITCH + c1q * 16, gp[mmat] + (size_t)r1 * K + c1q * 8);
        }
    };

    const uint32_t a_row  = m_warp + (lane & 15);
    const uint32_t a_byte = ((lane >> 4) & 1) * 16;
    const uint32_t b_row  = n_warp + ((lane >> 4) & 1) * 8 + (lane & 7);
    const uint32_t b_byte = ((lane >> 3) & 1) * 16;

    load_chunk(0, 0);
    CPA_COMMIT();
    CPA_WAIT0();
    __syncthreads();

    for (int c = 0; c < NCHUNK; c++) {
        const int s = c & 1;
        if (c + 1 < NCHUNK) { load_chunk(c + 1, s ^ 1); CPA_COMMIT(); }

        const uint32_t stg = sb + s * STAGE_BYTES;
        const uint32_t Am = stg, Bm = stg + MAT_BYTES;

#pragma unroll
        for (int ks = 0; ks < 2; ks++) {
            const uint32_t koff = ks * 32;
            uint32_t af[2][4];
#pragma unroll
            for (int mt = 0; mt < 2; mt++)
                LDM4(af[mt], Am + (a_row + mt * 16) * PITCH + koff + a_byte);
            uint32_t bf[4][4];
#pragma unroll
            for (int p = 0; p < 4; p++)
                LDM4(bf[p], Bm + (b_row + p * 16) * PITCH + koff + b_byte);
#pragma unroll
            for (int mt = 0; mt < 2; mt++)
#pragma unroll
                for (int nt = 0; nt < 8; nt++) {
                    const int p = nt >> 1, o = (nt & 1) * 2;
                    MMA_F16(acc[mt][nt], af[mt], bf[p][o], bf[p][o + 1]);
                }
        }
        if (c + 1 < NCHUNK) CPA_WAIT0();
        __syncthreads();
    }

    // ---- epilogue ----
    const int lr = lane >> 2;
    const int lc = (lane & 3) * 2;
    const float rscale = 0.08838834764831845f;   // 1/sqrt(128)

#pragma unroll
    for (int mt = 0; mt < 2; mt++) {
#pragma unroll
        for (int nt = 0; nt < 8; nt++) {
            const int ncol = n_warp + nt * 8 + lc;
            const float b0 = bias[n0 + ncol];
            const float b1 = bias[n0 + ncol + 1];
#pragma unroll
            for (int half = 0; half < 2; half++) {
                const int m = m0 + m_warp + mt * 16 + lr + half * 8;
                float v0 = acc[mt][nt][half * 2 + 0] + b0;
                float v1 = acc[mt][nt][half * 2 + 1] + b1;
                if (MODE == 0) {
                    *(float2*)&out0[(size_t)m * N + n0 + ncol] = make_float2(v0, v1);
                } else {
                    const int part = n0 >> 11;           // 0=q, 1=k, 2=v
                    const int hh   = (n0 & 2047) >> 7;
                    const int bb   = m >> 11;
                    const int ss   = m & 2047;
                    if (part < 2) {
                        const float cs0 = cosT[ss * Dd + ncol];
                        const float sn0 = sinT[ss * Dd + ncol];
                        const float cs1 = cosT[ss * Dd + ncol + 1];
                        const float sn1 = sinT[ss * Dd + ncol + 1];
                        const float e = v0, o = v1;
                        v0 = e * cs0 - o * sn0;
                        v1 = o * cs1 + e * sn1;
                    }
                    size_t idx = ((((size_t)bb * Hh + hh) * Ss) + ss) * Dd + ncol;
                    if (part == 0) {
                        float s0 = v0 * rscale, s1 = v1 * rscale;
                        uint32_t ph = pack_rn(s0, s1);
                        uint32_t pl = pack_rn(s0 - bf_lo(ph), s1 - bf_hi(ph));
                        *(uint32_t*)(qhp + idx) = ph;
                        *(uint32_t*)(qlp + idx) = pl;
                    } else {
                        float* dst = (part == 1) ? out1 : out2;
                        *(float2*)&dst[idx] = make_float2(v0, v1);
                        __nv_bfloat16* dh = (part == 1) ? khp : vhp;
                        __nv_bfloat16* dl = (part == 1) ? klp : vlp;
                        uint32_t ph = pack_rn(v0, v1);
                        uint32_t pl = pack_rn(v0 - bf_lo(ph), v1 - bf_hi(ph));
                        *(uint32_t*)(dh + idx) = ph;
                        *(uint32_t*)(dl + idx) = pl;
                    }
                }
            }
        }
    }
}

// ---------------------------------------------------------------------------
// Tensor-core flash attention (bf16 hi/lo, 3-pass, mma.sync). Exact R6 config:
// CTA = 128 q-rows of one (b,h); 8 warps x 16 rows; BK=64; D=128.
// K/V hi/lo double-buffered in smem via cp.async; V via ldmatrix.trans.
// Output y emitted as fp16 (feeds the single-pass fp16 proj GEMM).
// ---------------------------------------------------------------------------
#define AT_PITCH 272                 // 128 bf16 = 256B + 16B pad
#define AT_QBYTES (128 * AT_PITCH)   // 34816
#define AT_KBYTES (64 * AT_PITCH)    // 17408
#define AT_STAGE  (4 * AT_KBYTES)    // Kh,Kl,Vh,Vl = 69632
#define AT_SMEM   (2 * AT_QBYTES + 2 * AT_STAGE)   // 208896

__global__ void __launch_bounds__(256, 1)
mha_attn_mma(const __nv_bfloat16* __restrict__ qh, const __nv_bfloat16* __restrict__ ql,
             const __nv_bfloat16* __restrict__ kh, const __nv_bfloat16* __restrict__ kl,
             const __nv_bfloat16* __restrict__ vh, const __nv_bfloat16* __restrict__ vl,
             __half* __restrict__ yf)
{
    extern __shared__ char sm[];
    const uint32_t sb = smem_u32(sm);
    const int t = threadIdx.x, lane = t & 31, w = t >> 5;
    const int q0 = blockIdx.x * 128;
    const int h  = blockIdx.y, b = blockIdx.z;
    const size_t base = ((size_t)b * Hh + h) * (size_t)Ss * Dd;

    const uint32_t QH = sb, QL = sb + AT_QBYTES;
    const uint32_t ST0 = sb + 2 * AT_QBYTES;

    // ---- load Q hi/lo (128 rows x 256B each) ----
    {
        const __nv_bfloat16* sq[2] = { qh + base + (size_t)q0 * Dd,
                                       ql + base + (size_t)q0 * Dd };
#pragma unroll
        for (int mmat = 0; mmat < 2; mmat++) {
            const uint32_t dstb = mmat ? QL : QH;
#pragma unroll
            for (int j = 0; j < 8; j++) {
                int idx = t + j * 256;               // 2048 16B-chunks
                int r = idx >> 4, c = idx & 15;
                CPA16(dstb + r * AT_PITCH + c * 16, sq[mmat] + (size_t)r * Dd + c * 8);
            }
        }
    }

    auto load_kv = [&](int kt, int s) {
        const size_t off = base + (size_t)kt * 64 * Dd;
        const __nv_bfloat16* srcs[4] = { kh + off, kl + off, vh + off, vl + off };
        const uint32_t stb = ST0 + s * AT_STAGE;
#pragma unroll
        for (int mmat = 0; mmat < 4; mmat++)
#pragma unroll
            for (int j = 0; j < 4; j++) {
                int idx = t + j * 256;               // 1024 chunks per matrix
                int r = idx >> 4, c = idx & 15;
                CPA16(stb + mmat * AT_KBYTES + r * AT_PITCH + c * 16,
                      srcs[mmat] + (size_t)r * Dd + c * 8);
            }
    };

    load_kv(0, 0);
    CPA_COMMIT();
    CPA_WAIT0();
    __syncthreads();

    const int lr = lane >> 2, lcq = lane & 3;
    // ldmatrix address components
    const uint32_t qrow_off = (uint32_t)(w * 16 + (lane & 15)) * AT_PITCH + ((lane >> 4) & 1) * 16;
    const uint32_t krow_off = (uint32_t)(((lane >> 4) & 1) * 8 + (lane & 7)) * AT_PITCH + ((lane >> 3) & 1) * 16;
    const uint32_t vrow_off = (uint32_t)(lane & 15) * AT_PITCH + ((lane >> 4) & 1) * 16;

    float o[16][4];
#pragma unroll
    for (int i = 0; i < 16; i++)
#pragma unroll
        for (int j = 0; j < 4; j++) o[i][j] = 0.f;
    float mrow[2] = { -1e30f, -1e30f };
    float lrow[2] = { 0.f, 0.f };

    for (int kt = 0; kt < Ss / 64; kt++) {
        const int s = kt & 1;
        if (kt + 1 < Ss / 64) { load_kv(kt + 1, s ^ 1); CPA_COMMIT(); }

        const uint32_t KHs = ST0 + s * AT_STAGE;
        const uint32_t KLs = KHs + AT_KBYTES;
        const uint32_t VHs = KHs + 2 * AT_KBYTES;
        const uint32_t VLs = KHs + 3 * AT_KBYTES;

        // ---- S = Q K^T (hi/lo 3-pass), warp tile 16x64 ----
        float sc[8][4];
#pragma unroll
        for (int i = 0; i < 8; i++)
#pragma unroll
            for (int j = 0; j < 4; j++) sc[i][j] = 0.f;

#pragma unroll
        for (int ks = 0; ks < 8; ks++) {
            uint32_t ahf[4], alf[4];
            LDM4(ahf, QH + qrow_off + ks * 32);
            LDM4(alf, QL + qrow_off + ks * 32);
#pragma unroll
            for (int ntp = 0; ntp < 4; ntp++) {
                uint32_t bhf[4], blf[4];
                LDM4(bhf, KHs + ntp * 16 * AT_PITCH + krow_off + ks * 32);
                LDM4(blf, KLs + ntp * 16 * AT_PITCH + krow_off + ks * 32);
                MMA_BF16(sc[2 * ntp],     ahf, bhf[0], bhf[1]);
                MMA_BF16(sc[2 * ntp + 1], ahf, bhf[2], bhf[3]);
                MMA_BF16(sc[2 * ntp],     ahf, blf[0], blf[1]);
                MMA_BF16(sc[2 * ntp + 1], ahf, blf[2], blf[3]);
                MMA_BF16(sc[2 * ntp],     alf, bhf[0], bhf[1]);
                MMA_BF16(sc[2 * ntp + 1], alf, bhf[2], bhf[3]);
            }
        }

        // ---- online softmax (rows lr and lr+8; quad-local reductions) ----
#pragma unroll
        for (int r = 0; r < 2; r++) {
            float mx = -1e30f;
#pragma unroll
            for (int nt = 0; nt < 8; nt++)
                mx = fmaxf(mx, fmaxf(sc[nt][2 * r], sc[nt][2 * r + 1]));
            mx = fmaxf(mx, __shfl_xor_sync(0xffffffffu, mx, 1));
            mx = fmaxf(mx, __shfl_xor_sync(0xffffffffu, mx, 2));
            const float mn = fmaxf(mrow[r], mx);
            const float al = __expf(mrow[r] - mn);
            mrow[r] = mn;
            float rs = 0.f;
#pragma unroll
            for (int nt = 0; nt < 8; nt++) {
                float p0 = __expf(sc[nt][2 * r]     - mn);
                float p1 = __expf(sc[nt][2 * r + 1] - mn);
                sc[nt][2 * r] = p0; sc[nt][2 * r + 1] = p1;
                rs += p0 + p1;
            }
            rs += __shfl_xor_sync(0xffffffffu, rs, 1);
            rs += __shfl_xor_sync(0xffffffffu, rs, 2);
            lrow[r] = lrow[r] * al + rs;
#pragma unroll
            for (int nt = 0; nt < 16; nt++) {
                o[nt][2 * r] *= al; o[nt][2 * r + 1] *= al;
            }
        }

        // ---- O += P V (hi/lo 3-pass); P A-frags straight from sc regs ----
#pragma unroll
        for (int kg = 0; kg < 4; kg++) {
            uint32_t afh[4], afl[4];
#pragma unroll
            for (int u = 0; u < 2; u++) {          // u=0: ntile 2kg, u=1: ntile 2kg+1
                const float e0 = sc[2 * kg + u][0], e1 = sc[2 * kg + u][1];
                const float e2 = sc[2 * kg + u][2], e3 = sc[2 * kg + u][3];
                uint32_t h01 = pack_rn(e0, e1);
                uint32_t h23 = pack_rn(e2, e3);
                afh[2 * u]     = h01;
                afh[2 * u + 1] = h23;
                afl[2 * u]     = pack_rn(e0 - bf_lo(h01), e1 - bf_hi(h01));
                afl[2 * u + 1] = pack_rn(e2 - bf_lo(h23), e3 - bf_hi(h23));
            }
#pragma unroll
            for (int dg = 0; dg < 8; dg++) {
                uint32_t bh4[4], bl4[4];
                LDM4T(bh4, VHs + kg * 16 * AT_PITCH + vrow_off + dg * 32);
                LDM4T(bl4, VLs + kg * 16 * AT_PITCH + vrow_off + dg * 32);
                MMA_BF16(o[2 * dg],     afh, bh4[0], bh4[1]);
                MMA_BF16(o[2 * dg + 1], afh, bh4[2], bh4[3]);
                MMA_BF16(o[2 * dg],     afh, bl4[0], bl4[1]);
                MMA_BF16(o[2 * dg + 1], afh, bl4[2], bl4[3]);
                MMA_BF16(o[2 * dg],     afl, bh4[0], bh4[1]);
                MMA_BF16(o[2 * dg + 1], afl, bh4[2], bh4[3]);
            }
        }

        CPA_WAIT0();
        __syncthreads();
    }

    // ---- epilogue: scale by 1/l, emit fp16 y in (B,S,E) ----
    const float inv0 = 1.f / lrow[0];
    const float inv1 = 1.f / lrow[1];
    const int row0 = q0 + w * 16 + lr;
    const int row1 = row0 + 8;
#pragma unroll
    for (int nt = 0; nt < 16; nt++) {
        const int col = h * Dd + nt * 8 + 2 * lcq;
        {
            size_t idx = ((size_t)b * Ss + row0) * Ee + col;
            *(__half2*)(yf + idx) = __floats2half2_rn(o[nt][0] * inv0, o[nt][1] * inv0);
        }
        {
            size_t idx = ((size_t)b * Ss + row1) * Ee + col;
            *(__half2*)(yf + idx) = __floats2half2_rn(o[nt][2] * inv1, o[nt][3] * inv1);
        }
    }
}

// ---------------------------------------------------------------------------
extern "C" void kernel_launch(void* const* d_in, const int* in_sizes, int n_in,
                              void* d_out, int out_size)
{
    const float* x     = (const float*)d_in[0];
    const float* cosT  = (const float*)d_in[1];
    const float* sinT  = (const float*)d_in[2];
    const float* Wqkv  = (const float*)d_in[3];
    const float* bqkv  = (const float*)d_in[4];
    const float* Wproj = (const float*)d_in[5];
    const float* bproj = (const float*)d_in[6];

    float* out  = (float*)d_out;                 // (B,S,E)
    float* kout = out + HEAD_ELEMS;              // (B,H,S,D)
    float* vout = out + 2 * HEAD_ELEMS;          // (B,H,S,D)

    __half *xf, *wqf, *wpf, *yf;
    __nv_bfloat16 *qhp, *qlp, *khp, *klp, *vhp, *vlp;
    cudaGetSymbolAddress((void**)&xf,  g_xf);
    cudaGetSymbolAddress((void**)&wqf, g_wqkvf);
    cudaGetSymbolAddress((void**)&wpf, g_wprojf);
    cudaGetSymbolAddress((void**)&yf,  g_yf);
    cudaGetSymbolAddress((void**)&qhp, g_qh);
    cudaGetSymbolAddress((void**)&qlp, g_ql);
    cudaGetSymbolAddress((void**)&khp, g_kh);
    cudaGetSymbolAddress((void**)&klp, g_kl);
    cudaGetSymbolAddress((void**)&vhp, g_vh);
    cudaGetSymbolAddress((void**)&vlp, g_vl);

    // 0) conversions: x -> fp16, weights -> transposed fp16
    {
        const int n4 = (Mm * Ee) / 4;
        conv_half<<<(n4 + 255) / 256, 256>>>((const float4*)x, (__half2*)xf, n4);
        transpose_half<<<dim3(N_QKV / 32, Ee / 32), 256>>>(Wqkv, wqf, Ee, N_QKV);
        transpose_half<<<dim3(Ee / 32, Ee / 32), 256>>>(Wproj, wpf, Ee, Ee);
    }

    // 1) QKV GEMM (fp16 single-pass) + bias + RoPE: q (scaled) -> bf16 hi/lo;
    //    k,v -> fp32 out + bf16 hi/lo
    {
        cudaFuncSetAttribute(gemm_mma<1>, cudaFuncAttributeMaxDynamicSharedMemorySize, GEMM_SMEM);
        dim3 grid(N_QKV / 128, Mm / 128);
        gemm_mma<1><<<grid, 256, GEMM_SMEM>>>(xf, wqf, bqkv, cosT, sinT,
                                              nullptr, kout, vout,
                                              qhp, qlp, khp, klp, vhp, vlp, Ee, N_QKV);
    }

    // 2) Tensor-core flash attention (bf16 3-pass) -> fp16 y
    {
        cudaFuncSetAttribute(mha_attn_mma, cudaFuncAttributeMaxDynamicSharedMemorySize, AT_SMEM);
        dim3 grid(Ss / 128, Hh, Bb);
        mha_attn_mma<<<grid, 256, AT_SMEM>>>(qhp, qlp, khp, klp, vhp, vlp, yf);
    }

    // 3) Projection GEMM (fp16 single-pass) + bias
    {
        cudaFuncSetAttribute(gemm_mma<0>, cudaFuncAttributeMaxDynamicSharedMemorySize, GEMM_SMEM);
        dim3 grid(Ee / 128, Mm / 128);
        gemm_mma<0><<<grid, 256, GEMM_SMEM>>>(yf, wpf, bproj, nullptr, nullptr,
                                              out, nullptr, nullptr,
                                              nullptr, nullptr, nullptr, nullptr,
                                              nullptr, nullptr, Ee, Ee);
    }
}

// round 13
// speedup vs baseline: 2.0421x; 1.1744x over previous
#include <cuda_runtime.h>
#include <cuda_bf16.h>
#include <cuda_fp16.h>
#include <cstdint>

// Problem constants
#define Bb 4
#define Ss 2048
#define Ee 2048
#define Hh 16
#define Dd 128
#define Mm (Bb * Ss)          // 8192
#define N_QKV (3 * Ee)        // 6144
#define HEAD_ELEMS ((size_t)Bb * Hh * Ss * Dd)   // 16,777,216

// ---------------------------------------------------------------------------
// Scratch (device globals; no allocation allowed)
// ---------------------------------------------------------------------------
__device__ __nv_bfloat16 g_qh[HEAD_ELEMS], g_ql[HEAD_ELEMS];     // q hi/lo (B,H,S,D), pre-scaled
__device__ __nv_bfloat16 g_kh[HEAD_ELEMS], g_kl[HEAD_ELEMS];     // k hi/lo
__device__ __half g_vf[HEAD_ELEMS];                              // v fp16
__device__ __half g_xf[(size_t)Mm * Ee];                         // x fp16
__device__ __half g_wqkvf[(size_t)N_QKV * Ee];                   // Wqkv^T fp16 [N,K]
__device__ __half g_wprojf[(size_t)Ee * Ee];                     // Wproj^T fp16 [N,K]
__device__ __half g_yf[(size_t)Mm * Ee];                         // attn out fp16 (B,S,E)

// ---------------------------------------------------------------------------
// PTX helpers (sm_80-era: mma.sync / ldmatrix / cp.async — legal on sm_103 base)
// ---------------------------------------------------------------------------
__device__ __forceinline__ uint32_t smem_u32(const void* p) {
    uint32_t a;
    asm("{ .reg .u64 t; cvta.to.shared.u64 t, %1; cvt.u32.u64 %0, t; }" : "=r"(a) : "l"(p));
    return a;
}

#define LDM4(r, addr)                                                          \
    asm volatile("ldmatrix.sync.aligned.m8n8.x4.shared.b16 {%0,%1,%2,%3}, [%4];" \
                 : "=r"((r)[0]), "=r"((r)[1]), "=r"((r)[2]), "=r"((r)[3])      \
                 : "r"(addr))

#define LDM4T(r, addr)                                                         \
    asm volatile("ldmatrix.sync.aligned.m8n8.x4.trans.shared.b16 {%0,%1,%2,%3}, [%4];" \
                 : "=r"((r)[0]), "=r"((r)[1]), "=r"((r)[2]), "=r"((r)[3])      \
                 : "r"(addr))

#define MMA_BF16(d, a, b0, b1)                                                 \
    asm volatile("mma.sync.aligned.m16n8k16.row.col.f32.bf16.bf16.f32 "        \
                 "{%0,%1,%2,%3}, {%4,%5,%6,%7}, {%8,%9}, {%0,%1,%2,%3};"       \
                 : "+f"((d)[0]), "+f"((d)[1]), "+f"((d)[2]), "+f"((d)[3])      \
                 : "r"((a)[0]), "r"((a)[1]), "r"((a)[2]), "r"((a)[3]),         \
                   "r"(b0), "r"(b1))

#define MMA_F16(d, a, b0, b1)                                                  \
    asm volatile("mma.sync.aligned.m16n8k16.row.col.f32.f16.f16.f32 "          \
                 "{%0,%1,%2,%3}, {%4,%5,%6,%7}, {%8,%9}, {%0,%1,%2,%3};"       \
                 : "+f"((d)[0]), "+f"((d)[1]), "+f"((d)[2]), "+f"((d)[3])      \
                 : "r"((a)[0]), "r"((a)[1]), "r"((a)[2]), "r"((a)[3]),         \
                   "r"(b0), "r"(b1))

#define CPA16(dst, src)                                                        \
    asm volatile("cp.async.cg.shared.global [%0], [%1], 16;"                   \
                 :: "r"(dst), "l"(src) : "memory")
#define CPA_COMMIT() asm volatile("cp.async.commit_group;" ::: "memory")
#define CPA_WAIT0()  asm volatile("cp.async.wait_group 0;" ::: "memory")

// pack two fp32 -> bf16x2, round-to-nearest
__device__ __forceinline__ uint32_t pack_rn(float lo, float hi) {
    uint32_t r;
    asm("cvt.rn.bf16x2.f32 %0, %1, %2;" : "=r"(r) : "f"(hi), "f"(lo));
    return r;
}
__device__ __forceinline__ float bf_lo(uint32_t r) { return __uint_as_float(r << 16); }
__device__ __forceinline__ float bf_hi(uint32_t r) { return __uint_as_float(r & 0xFFFF0000u); }
// pack two fp32 -> fp16x2
__device__ __forceinline__ uint32_t pack_h2(float lo, float hi) {
    __half2 h = __floats2half2_rn(lo, hi);
    return *(uint32_t*)&h;
}

// ---------------------------------------------------------------------------
// Conversion kernels
// ---------------------------------------------------------------------------
__global__ void __launch_bounds__(256)
conv_half(const float4* __restrict__ in, __half2* __restrict__ o, int n4)
{
    int i = blockIdx.x * 256 + threadIdx.x;
    if (i >= n4) return;
    float4 v = in[i];
    o[2 * i]     = __floats2half2_rn(v.x, v.y);
    o[2 * i + 1] = __floats2half2_rn(v.z, v.w);
}

// W [K,N] fp32 -> out [N,K] fp16
__global__ void __launch_bounds__(256)
transpose_half(const float* __restrict__ W, __half* __restrict__ th, int K, int N)
{
    __shared__ float tile[32][33];
    const int n0 = blockIdx.x * 32, k0 = blockIdx.y * 32;
    const int tx = threadIdx.x & 31, ty = threadIdx.x >> 5;
#pragma unroll
    for (int r = ty; r < 32; r += 8)
        tile[r][tx] = W[(size_t)(k0 + r) * N + n0 + tx];
    __syncthreads();
#pragma unroll
    for (int r = ty; r < 32; r += 8)
        th[(size_t)(n0 + r) * K + k0 + tx] = __float2half_rn(tile[tx][r]);
}

// ---------------------------------------------------------------------------
// mma.sync fp16 single-pass GEMM: C[M,N] = A[M,K] * B^T (B stored [N,K]),
// fp32 accum. CTA 128x128, 8 warps (4x2), warp tile 32x64, K chunks of 32,
// cp.async double-buffered smem (40KB), 80B row pitch.
// MODE 0: out0 = C + bias (proj).
// MODE 1: QKV epilogue — bias, RoPE, q*scale -> bf16 hi/lo; k -> fp32 + bf16
//         hi/lo; v -> fp32 + fp16.
// ---------------------------------------------------------------------------
#define PITCH 80                       // bytes per 32-elem fp16 row (64B + 16B pad)
#define MAT_BYTES (128 * PITCH)        // 10240
#define STAGE_BYTES (2 * MAT_BYTES)    // A, B = 20480
#define GEMM_SMEM (2 * STAGE_BYTES)    // 40960

template <int MODE>
__global__ void __launch_bounds__(256)
gemm_mma(const __half* __restrict__ Ag, const __half* __restrict__ Bg,
         const float* __restrict__ bias,
         const float* __restrict__ cosT, const float* __restrict__ sinT,
         float* __restrict__ out0, float* __restrict__ out1, float* __restrict__ out2,
         __nv_bfloat16* __restrict__ qhp, __nv_bfloat16* __restrict__ qlp,
         __nv_bfloat16* __restrict__ khp, __nv_bfloat16* __restrict__ klp,
         __half* __restrict__ vfp,
         int K, int N)
{
    extern __shared__ char sm[];
    const uint32_t sb = smem_u32(sm);
    const int t    = threadIdx.x;
    const int lane = t & 31;
    const int wid  = t >> 5;
    const int m0   = blockIdx.y * 128;
    const int n0   = blockIdx.x * 128;
    const int m_warp = (wid & 3) * 32;
    const int n_warp = (wid >> 2) * 64;

    float acc[2][8][4];
#pragma unroll
    for (int i = 0; i < 2; i++)
#pragma unroll
        for (int j = 0; j < 8; j++)
#pragma unroll
            for (int k = 0; k < 4; k++) acc[i][j][k] = 0.f;

    const int q0i = t, q1i = t + 256;
    const int r0 = q0i >> 2, c0q = q0i & 3;
    const int r1 = q1i >> 2, c1q = q1i & 3;

    const int NCHUNK = K / 32;

    auto load_chunk = [&](int c, int s) {
        const uint32_t stg = sb + s * STAGE_BYTES;
        const int k0 = c * 32;
        const __half* gp[2] = { Ag + (size_t)m0 * K + k0, Bg + (size_t)n0 * K + k0 };
#pragma unroll
        for (int mmat = 0; mmat < 2; mmat++) {
            const uint32_t mb = stg + mmat * MAT_BYTES;
            CPA16(mb + r0 * PITCH + c0q * 16, gp[mmat] + (size_t)r0 * K + c0q * 8);
            CPA16(mb + r1 * PITCH + c1q * 16, gp[mmat] + (size_t)r1 * K + c1q * 8);
        }
    };

    const uint32_t a_row  = m_warp + (lane & 15);
    const uint32_t a_byte = ((lane >> 4) & 1) * 16;
    const uint32_t b_row  = n_warp + ((lane >> 4) & 1) * 8 + (lane & 7);
    const uint32_t b_byte = ((lane >> 3) & 1) * 16;

    load_chunk(0, 0);
    CPA_COMMIT();
    CPA_WAIT0();
    __syncthreads();

    for (int c = 0; c < NCHUNK; c++) {
        const int s = c & 1;
        if (c + 1 < NCHUNK) { load_chunk(c + 1, s ^ 1); CPA_COMMIT(); }

        const uint32_t stg = sb + s * STAGE_BYTES;
        const uint32_t Am = stg, Bm = stg + MAT_BYTES;

#pragma unroll
        for (int ks = 0; ks < 2; ks++) {
            const uint32_t koff = ks * 32;
            uint32_t af[2][4];
#pragma unroll
            for (int mt = 0; mt < 2; mt++)
                LDM4(af[mt], Am + (a_row + mt * 16) * PITCH + koff + a_byte);
            uint32_t bf[4][4];
#pragma unroll
            for (int p = 0; p < 4; p++)
                LDM4(bf[p], Bm + (b_row + p * 16) * PITCH + koff + b_byte);
#pragma unroll
            for (int mt = 0; mt < 2; mt++)
#pragma unroll
                for (int nt = 0; nt < 8; nt++) {
                    const int p = nt >> 1, o = (nt & 1) * 2;
                    MMA_F16(acc[mt][nt], af[mt], bf[p][o], bf[p][o + 1]);
                }
        }
        if (c + 1 < NCHUNK) CPA_WAIT0();
        __syncthreads();
    }

    // ---- epilogue ----
    const int lr = lane >> 2;
    const int lc = (lane & 3) * 2;
    const float rscale = 0.08838834764831845f;   // 1/sqrt(128)

#pragma unroll
    for (int mt = 0; mt < 2; mt++) {
#pragma unroll
        for (int nt = 0; nt < 8; nt++) {
            const int ncol = n_warp + nt * 8 + lc;
            const float b0 = bias[n0 + ncol];
            const float b1 = bias[n0 + ncol + 1];
#pragma unroll
            for (int half = 0; half < 2; half++) {
                const int m = m0 + m_warp + mt * 16 + lr + half * 8;
                float v0 = acc[mt][nt][half * 2 + 0] + b0;
                float v1 = acc[mt][nt][half * 2 + 1] + b1;
                if (MODE == 0) {
                    *(float2*)&out0[(size_t)m * N + n0 + ncol] = make_float2(v0, v1);
                } else {
                    const int part = n0 >> 11;           // 0=q, 1=k, 2=v
                    const int hh   = (n0 & 2047) >> 7;
                    const int bb   = m >> 11;
                    const int ss   = m & 2047;
                    if (part < 2) {
                        const float cs0 = cosT[ss * Dd + ncol];
                        const float sn0 = sinT[ss * Dd + ncol];
                        const float cs1 = cosT[ss * Dd + ncol + 1];
                        const float sn1 = sinT[ss * Dd + ncol + 1];
                        const float e = v0, o = v1;
                        v0 = e * cs0 - o * sn0;
                        v1 = o * cs1 + e * sn1;
                    }
                    size_t idx = ((((size_t)bb * Hh + hh) * Ss) + ss) * Dd + ncol;
                    if (part == 0) {
                        float s0 = v0 * rscale, s1 = v1 * rscale;
                        uint32_t ph = pack_rn(s0, s1);
                        uint32_t pl = pack_rn(s0 - bf_lo(ph), s1 - bf_hi(ph));
                        *(uint32_t*)(qhp + idx) = ph;
                        *(uint32_t*)(qlp + idx) = pl;
                    } else if (part == 1) {
                        *(float2*)&out1[idx] = make_float2(v0, v1);
                        uint32_t ph = pack_rn(v0, v1);
                        uint32_t pl = pack_rn(v0 - bf_lo(ph), v1 - bf_hi(ph));
                        *(uint32_t*)(khp + idx) = ph;
                        *(uint32_t*)(klp + idx) = pl;
                    } else {
                        *(float2*)&out2[idx] = make_float2(v0, v1);
                        *(uint32_t*)(vfp + idx) = pack_h2(v0, v1);
                    }
                }
            }
        }
    }
}

// ---------------------------------------------------------------------------
// Tensor-core flash attention: QK^T bf16 hi/lo 3-pass (score precision),
// P·V fp16 single-pass (P in (0,1], V fp16 — rounding ~1e-4 in y).
// CTA = 128 q-rows of one (b,h); 8 warps x 16 rows; BK=64; D=128.
// K hi/lo + V fp16 double-buffered via cp.async; V via ldmatrix.trans.
// ---------------------------------------------------------------------------
#define AT_PITCH 272                 // 128 elems = 256B + 16B pad
#define AT_QBYTES (128 * AT_PITCH)   // 34816
#define AT_KBYTES (64 * AT_PITCH)    // 17408
#define AT_STAGE  (3 * AT_KBYTES)    // Kh, Kl, Vf = 52224
#define AT_SMEM   (2 * AT_QBYTES + 2 * AT_STAGE)   // 174080

__global__ void __launch_bounds__(256, 1)
mha_attn_mma(const __nv_bfloat16* __restrict__ qh, const __nv_bfloat16* __restrict__ ql,
             const __nv_bfloat16* __restrict__ kh, const __nv_bfloat16* __restrict__ kl,
             const __half* __restrict__ vf,
             __half* __restrict__ yf)
{
    extern __shared__ char sm[];
    const uint32_t sb = smem_u32(sm);
    const int t = threadIdx.x, lane = t & 31, w = t >> 5;
    const int q0 = blockIdx.x * 128;
    const int h  = blockIdx.y, b = blockIdx.z;
    const size_t base = ((size_t)b * Hh + h) * (size_t)Ss * Dd;

    const uint32_t QH = sb, QL = sb + AT_QBYTES;
    const uint32_t ST0 = sb + 2 * AT_QBYTES;

    // ---- load Q hi/lo (128 rows x 256B each) ----
    {
        const __nv_bfloat16* sq[2] = { qh + base + (size_t)q0 * Dd,
                                       ql + base + (size_t)q0 * Dd };
#pragma unroll
        for (int mmat = 0; mmat < 2; mmat++) {
            const uint32_t dstb = mmat ? QL : QH;
#pragma unroll
            for (int j = 0; j < 8; j++) {
                int idx = t + j * 256;               // 2048 16B-chunks
                int r = idx >> 4, c = idx & 15;
                CPA16(dstb + r * AT_PITCH + c * 16, sq[mmat] + (size_t)r * Dd + c * 8);
            }
        }
    }

    auto load_kv = [&](int kt, int s) {
        const size_t off = base + (size_t)kt * 64 * Dd;
        const uint32_t stb = ST0 + s * AT_STAGE;
        const __nv_bfloat16* kb[2] = { kh + off, kl + off };
#pragma unroll
        for (int mmat = 0; mmat < 2; mmat++)
#pragma unroll
            for (int j = 0; j < 4; j++) {
                int idx = t + j * 256;               // 1024 chunks per matrix
                int r = idx >> 4, c = idx & 15;
                CPA16(stb + mmat * AT_KBYTES + r * AT_PITCH + c * 16,
                      kb[mmat] + (size_t)r * Dd + c * 8);
            }
        const __half* vb = vf + off;
#pragma unroll
        for (int j = 0; j < 4; j++) {
            int idx = t + j * 256;
            int r = idx >> 4, c = idx & 15;
            CPA16(stb + 2 * AT_KBYTES + r * AT_PITCH + c * 16, vb + (size_t)r * Dd + c * 8);
        }
    };

    load_kv(0, 0);
    CPA_COMMIT();
    CPA_WAIT0();
    __syncthreads();

    const int lr = lane >> 2, lcq = lane & 3;
    // ldmatrix address components
    const uint32_t qrow_off = (uint32_t)(w * 16 + (lane & 15)) * AT_PITCH + ((lane >> 4) & 1) * 16;
    const uint32_t krow_off = (uint32_t)(((lane >> 4) & 1) * 8 + (lane & 7)) * AT_PITCH + ((lane >> 3) & 1) * 16;
    const uint32_t vrow_off = (uint32_t)(lane & 15) * AT_PITCH + ((lane >> 4) & 1) * 16;

    float o[16][4];
#pragma unroll
    for (int i = 0; i < 16; i++)
#pragma unroll
        for (int j = 0; j < 4; j++) o[i][j] = 0.f;
    float mrow[2] = { -1e30f, -1e30f };
    float lrow[2] = { 0.f, 0.f };

    for (int kt = 0; kt < Ss / 64; kt++) {
        const int s = kt & 1;
        if (kt + 1 < Ss / 64) { load_kv(kt + 1, s ^ 1); CPA_COMMIT(); }

        const uint32_t KHs = ST0 + s * AT_STAGE;
        const uint32_t KLs = KHs + AT_KBYTES;
        const uint32_t VFs = KHs + 2 * AT_KBYTES;

        // ---- S = Q K^T (hi/lo 3-pass), warp tile 16x64 ----
        float sc[8][4];
#pragma unroll
        for (int i = 0; i < 8; i++)
#pragma unroll
            for (int j = 0; j < 4; j++) sc[i][j] = 0.f;

#pragma unroll
        for (int ks = 0; ks < 8; ks++) {
            uint32_t ahf[4], alf[4];
            LDM4(ahf, QH + qrow_off + ks * 32);
            LDM4(alf, QL + qrow_off + ks * 32);
#pragma unroll
            for (int ntp = 0; ntp < 4; ntp++) {
                uint32_t bhf[4], blf[4];
                LDM4(bhf, KHs + ntp * 16 * AT_PITCH + krow_off + ks * 32);
                LDM4(blf, KLs + ntp * 16 * AT_PITCH + krow_off + ks * 32);
                MMA_BF16(sc[2 * ntp],     ahf, bhf[0], bhf[1]);
                MMA_BF16(sc[2 * ntp + 1], ahf, bhf[2], bhf[3]);
                MMA_BF16(sc[2 * ntp],     ahf, blf[0], blf[1]);
                MMA_BF16(sc[2 * ntp + 1], ahf, blf[2], blf[3]);
                MMA_BF16(sc[2 * ntp],     alf, bhf[0], bhf[1]);
                MMA_BF16(sc[2 * ntp + 1], alf, bhf[2], bhf[3]);
            }
        }

        // ---- online softmax (rows lr and lr+8; quad-local reductions) ----
#pragma unroll
        for (int r = 0; r < 2; r++) {
            float mx = -1e30f;
#pragma unroll
            for (int nt = 0; nt < 8; nt++)
                mx = fmaxf(mx, fmaxf(sc[nt][2 * r], sc[nt][2 * r + 1]));
            mx = fmaxf(mx, __shfl_xor_sync(0xffffffffu, mx, 1));
            mx = fmaxf(mx, __shfl_xor_sync(0xffffffffu, mx, 2));
            const float mn = fmaxf(mrow[r], mx);
            const float al = __expf(mrow[r] - mn);
            mrow[r] = mn;
            float rs = 0.f;
#pragma unroll
            for (int nt = 0; nt < 8; nt++) {
                float p0 = __expf(sc[nt][2 * r]     - mn);
                float p1 = __expf(sc[nt][2 * r + 1] - mn);
                sc[nt][2 * r] = p0; sc[nt][2 * r + 1] = p1;
                rs += p0 + p1;
            }
            rs += __shfl_xor_sync(0xffffffffu, rs, 1);
            rs += __shfl_xor_sync(0xffffffffu, rs, 2);
            lrow[r] = lrow[r] * al + rs;
#pragma unroll
            for (int nt = 0; nt < 16; nt++) {
                o[nt][2 * r] *= al; o[nt][2 * r + 1] *= al;
            }
        }

        // ---- O += P V (fp16 single-pass); P A-frags straight from sc regs ----
#pragma unroll
        for (int kg = 0; kg < 4; kg++) {
            uint32_t af[4];
#pragma unroll
            for (int u = 0; u < 2; u++) {          // u=0: ntile 2kg, u=1: ntile 2kg+1
                af[2 * u]     = pack_h2(sc[2 * kg + u][0], sc[2 * kg + u][1]);
                af[2 * u + 1] = pack_h2(sc[2 * kg + u][2], sc[2 * kg + u][3]);
            }
#pragma unroll
            for (int dg = 0; dg < 8; dg++) {
                uint32_t bv[4];
                LDM4T(bv, VFs + kg * 16 * AT_PITCH + vrow_off + dg * 32);
                MMA_F16(o[2 * dg],     af, bv[0], bv[1]);
                MMA_F16(o[2 * dg + 1], af, bv[2], bv[3]);
            }
        }

        CPA_WAIT0();
        __syncthreads();
    }

    // ---- epilogue: scale by 1/l, emit fp16 y in (B,S,E) ----
    const float inv0 = 1.f / lrow[0];
    const float inv1 = 1.f / lrow[1];
    const int row0 = q0 + w * 16 + lr;
    const int row1 = row0 + 8;
#pragma unroll
    for (int nt = 0; nt < 16; nt++) {
        const int col = h * Dd + nt * 8 + 2 * lcq;
        {
            size_t idx = ((size_t)b * Ss + row0) * Ee + col;
            *(__half2*)(yf + idx) = __floats2half2_rn(o[nt][0] * inv0, o[nt][1] * inv0);
        }
        {
            size_t idx = ((size_t)b * Ss + row1) * Ee + col;
            *(__half2*)(yf + idx) = __floats2half2_rn(o[nt][2] * inv1, o[nt][3] * inv1);
        }
    }
}

// ---------------------------------------------------------------------------
extern "C" void kernel_launch(void* const* d_in, const int* in_sizes, int n_in,
                              void* d_out, int out_size)
{
    const float* x     = (const float*)d_in[0];
    const float* cosT  = (const float*)d_in[1];
    const float* sinT  = (const float*)d_in[2];
    const float* Wqkv  = (const float*)d_in[3];
    const float* bqkv  = (const float*)d_in[4];
    const float* Wproj = (const float*)d_in[5];
    const float* bproj = (const float*)d_in[6];

    float* out  = (float*)d_out;                 // (B,S,E)
    float* kout = out + HEAD_ELEMS;              // (B,H,S,D)
    float* vout = out + 2 * HEAD_ELEMS;          // (B,H,S,D)

    __half *xf, *wqf, *wpf, *yf, *vfp;
    __nv_bfloat16 *qhp, *qlp, *khp, *klp;
    cudaGetSymbolAddress((void**)&xf,  g_xf);
    cudaGetSymbolAddress((void**)&wqf, g_wqkvf);
    cudaGetSymbolAddress((void**)&wpf, g_wprojf);
    cudaGetSymbolAddress((void**)&yf,  g_yf);
    cudaGetSymbolAddress((void**)&qhp, g_qh);
    cudaGetSymbolAddress((void**)&qlp, g_ql);
    cudaGetSymbolAddress((void**)&khp, g_kh);
    cudaGetSymbolAddress((void**)&klp, g_kl);
    cudaGetSymbolAddress((void**)&vfp, g_vf);

    // 0) conversions: x -> fp16, weights -> transposed fp16
    {
        const int n4 = (Mm * Ee) / 4;
        conv_half<<<(n4 + 255) / 256, 256>>>((const float4*)x, (__half2*)xf, n4);
        transpose_half<<<dim3(N_QKV / 32, Ee / 32), 256>>>(Wqkv, wqf, Ee, N_QKV);
        transpose_half<<<dim3(Ee / 32, Ee / 32), 256>>>(Wproj, wpf, Ee, Ee);
    }

    // 1) QKV GEMM (fp16 single-pass) + bias + RoPE: q (scaled) -> bf16 hi/lo;
    //    k -> fp32 out + bf16 hi/lo; v -> fp32 out + fp16
    {
        cudaFuncSetAttribute(gemm_mma<1>, cudaFuncAttributeMaxDynamicSharedMemorySize, GEMM_SMEM);
        dim3 grid(N_QKV / 128, Mm / 128);
        gemm_mma<1><<<grid, 256, GEMM_SMEM>>>(xf, wqf, bqkv, cosT, sinT,
                                              nullptr, kout, vout,
                                              qhp, qlp, khp, klp, vfp, Ee, N_QKV);
    }

    // 2) Flash attention: QK bf16 3-pass, PV fp16 single-pass -> fp16 y
    {
        cudaFuncSetAttribute(mha_attn_mma, cudaFuncAttributeMaxDynamicSharedMemorySize, AT_SMEM);
        dim3 grid(Ss / 128, Hh, Bb);
        mha_attn_mma<<<grid, 256, AT_SMEM>>>(qhp, qlp, khp, klp, vfp, yf);
    }

    // 3) Projection GEMM (fp16 single-pass) + bias
    {
        cudaFuncSetAttribute(gemm_mma<0>, cudaFuncAttributeMaxDynamicSharedMemorySize, GEMM_SMEM);
        dim3 grid(Ee / 128, Mm / 128);
        gemm_mma<0><<<grid, 256, GEMM_SMEM>>>(yf, wpf, bproj, nullptr, nullptr,
                                              out, nullptr, nullptr,
                                              nullptr, nullptr, nullptr, nullptr,
                                              nullptr, Ee, Ee);
    }
}

// round 14
// speedup vs baseline: 2.0865x; 1.0217x over previous
#include <cuda_runtime.h>
#include <cuda_bf16.h>
#include <cuda_fp16.h>
#include <cstdint>

// Problem constants
#define Bb 4
#define Ss 2048
#define Ee 2048
#define Hh 16
#define Dd 128
#define Mm (Bb * Ss)          // 8192
#define N_QKV (3 * Ee)        // 6144
#define HEAD_ELEMS ((size_t)Bb * Hh * Ss * Dd)   // 16,777,216

// ---------------------------------------------------------------------------
// Scratch (device globals; no allocation allowed)
// ---------------------------------------------------------------------------
__device__ __nv_bfloat16 g_qh[HEAD_ELEMS], g_ql[HEAD_ELEMS];     // q hi/lo (B,H,S,D), pre-scaled
__device__ __nv_bfloat16 g_kh[HEAD_ELEMS], g_kl[HEAD_ELEMS];     // k hi/lo
__device__ __half g_vf[HEAD_ELEMS];                              // v fp16
__device__ __half g_xf[(size_t)Mm * Ee];                         // x fp16
__device__ __half g_wqkvf[(size_t)N_QKV * Ee];                   // Wqkv^T fp16 [N,K]
__device__ __half g_wprojf[(size_t)Ee * Ee];                     // Wproj^T fp16 [N,K]
__device__ __half g_yf[(size_t)Mm * Ee];                         // attn out fp16 (B,S,E)

// ---------------------------------------------------------------------------
// PTX helpers (sm_80-era: mma.sync / ldmatrix / cp.async — legal on sm_103 base)
// ---------------------------------------------------------------------------
__device__ __forceinline__ uint32_t smem_u32(const void* p) {
    uint32_t a;
    asm("{ .reg .u64 t; cvta.to.shared.u64 t, %1; cvt.u32.u64 %0, t; }" : "=r"(a) : "l"(p));
    return a;
}

#define LDM4(r, addr)                                                          \
    asm volatile("ldmatrix.sync.aligned.m8n8.x4.shared.b16 {%0,%1,%2,%3}, [%4];" \
                 : "=r"((r)[0]), "=r"((r)[1]), "=r"((r)[2]), "=r"((r)[3])      \
                 : "r"(addr))

#define LDM4T(r, addr)                                                         \
    asm volatile("ldmatrix.sync.aligned.m8n8.x4.trans.shared.b16 {%0,%1,%2,%3}, [%4];" \
                 : "=r"((r)[0]), "=r"((r)[1]), "=r"((r)[2]), "=r"((r)[3])      \
                 : "r"(addr))

#define MMA_BF16(d, a, b0, b1)                                                 \
    asm volatile("mma.sync.aligned.m16n8k16.row.col.f32.bf16.bf16.f32 "        \
                 "{%0,%1,%2,%3}, {%4,%5,%6,%7}, {%8,%9}, {%0,%1,%2,%3};"       \
                 : "+f"((d)[0]), "+f"((d)[1]), "+f"((d)[2]), "+f"((d)[3])      \
                 : "r"((a)[0]), "r"((a)[1]), "r"((a)[2]), "r"((a)[3]),         \
                   "r"(b0), "r"(b1))

#define MMA_F16(d, a, b0, b1)                                                  \
    asm volatile("mma.sync.aligned.m16n8k16.row.col.f32.f16.f16.f32 "          \
                 "{%0,%1,%2,%3}, {%4,%5,%6,%7}, {%8,%9}, {%0,%1,%2,%3};"       \
                 : "+f"((d)[0]), "+f"((d)[1]), "+f"((d)[2]), "+f"((d)[3])      \
                 : "r"((a)[0]), "r"((a)[1]), "r"((a)[2]), "r"((a)[3]),         \
                   "r"(b0), "r"(b1))

#define CPA16(dst, src)                                                        \
    asm volatile("cp.async.cg.shared.global [%0], [%1], 16;"                   \
                 :: "r"(dst), "l"(src) : "memory")
#define CPA_COMMIT() asm volatile("cp.async.commit_group;" ::: "memory")
#define CPA_WAIT0()  asm volatile("cp.async.wait_group 0;" ::: "memory")

// pack two fp32 -> bf16x2, round-to-nearest
__device__ __forceinline__ uint32_t pack_rn(float lo, float hi) {
    uint32_t r;
    asm("cvt.rn.bf16x2.f32 %0, %1, %2;" : "=r"(r) : "f"(hi), "f"(lo));
    return r;
}
__device__ __forceinline__ float bf_lo(uint32_t r) { return __uint_as_float(r << 16); }
__device__ __forceinline__ float bf_hi(uint32_t r) { return __uint_as_float(r & 0xFFFF0000u); }
// pack two fp32 -> fp16x2
__device__ __forceinline__ uint32_t pack_h2(float lo, float hi) {
    __half2 h = __floats2half2_rn(lo, hi);
    return *(uint32_t*)&h;
}

// ---------------------------------------------------------------------------
// Conversion kernels
// ---------------------------------------------------------------------------
__global__ void __launch_bounds__(256)
conv_half(const float4* __restrict__ in, __half2* __restrict__ o, int n4)
{
    int i = blockIdx.x * 256 + threadIdx.x;
    if (i >= n4) return;
    float4 v = in[i];
    o[2 * i]     = __floats2half2_rn(v.x, v.y);
    o[2 * i + 1] = __floats2half2_rn(v.z, v.w);
}

// W [K,N] fp32 -> out [N,K] fp16
__global__ void __launch_bounds__(256)
transpose_half(const float* __restrict__ W, __half* __restrict__ th, int K, int N)
{
    __shared__ float tile[32][33];
    const int n0 = blockIdx.x * 32, k0 = blockIdx.y * 32;
    const int tx = threadIdx.x & 31, ty = threadIdx.x >> 5;
#pragma unroll
    for (int r = ty; r < 32; r += 8)
        tile[r][tx] = W[(size_t)(k0 + r) * N + n0 + tx];
    __syncthreads();
#pragma unroll
    for (int r = ty; r < 32; r += 8)
        th[(size_t)(n0 + r) * K + k0 + tx] = __float2half_rn(tile[tx][r]);
}

// ---------------------------------------------------------------------------
// mma.sync fp16 single-pass GEMM: C[M,N] = A[M,K] * B^T (B stored [N,K]),
// fp32 accum. CTA tile 128x128, 4 warps (2x2), warp tile 64x64, K chunks
// of 32, cp.async double-buffered smem (40KB -> 2 CTAs/SM), 80B row pitch.
// 64x64 warp tile: 8 LDM4 per 32 MMAs (vs 12 per 16 at 32x64) — 3x less
// smem crossbar traffic per MMA, targeting the measured L1=54.5% limiter.
// MODE 0: out0 = C + bias (proj).
// MODE 1: QKV epilogue — bias, RoPE, q*scale -> bf16 hi/lo; k -> fp32 + bf16
//         hi/lo; v -> fp32 + fp16.
// ---------------------------------------------------------------------------
#define PITCH 80                       // bytes per 32-elem fp16 row (64B + 16B pad)
#define MAT_BYTES (128 * PITCH)        // 10240
#define STAGE_BYTES (2 * MAT_BYTES)    // A, B = 20480
#define GEMM_SMEM (2 * STAGE_BYTES)    // 40960

template <int MODE>
__global__ void __launch_bounds__(128, 2)
gemm_mma(const __half* __restrict__ Ag, const __half* __restrict__ Bg,
         const float* __restrict__ bias,
         const float* __restrict__ cosT, const float* __restrict__ sinT,
         float* __restrict__ out0, float* __restrict__ out1, float* __restrict__ out2,
         __nv_bfloat16* __restrict__ qhp, __nv_bfloat16* __restrict__ qlp,
         __nv_bfloat16* __restrict__ khp, __nv_bfloat16* __restrict__ klp,
         __half* __restrict__ vfp,
         int K, int N)
{
    extern __shared__ char sm[];
    const uint32_t sb = smem_u32(sm);
    const int t    = threadIdx.x;
    const int lane = t & 31;
    const int wid  = t >> 5;                 // 0..3
    const int m0   = blockIdx.y * 128;
    const int n0   = blockIdx.x * 128;
    const int m_warp = (wid & 1) * 64;
    const int n_warp = (wid >> 1) * 64;

    float acc[4][8][4];
#pragma unroll
    for (int i = 0; i < 4; i++)
#pragma unroll
        for (int j = 0; j < 8; j++)
#pragma unroll
            for (int k = 0; k < 4; k++) acc[i][j][k] = 0.f;

    const int NCHUNK = K / 32;

    // each matrix: 128 rows x 4 quads = 512 quads; 128 threads -> 4 per thread
    auto load_chunk = [&](int c, int s) {
        const uint32_t stg = sb + s * STAGE_BYTES;
        const int k0 = c * 32;
        const __half* gp[2] = { Ag + (size_t)m0 * K + k0, Bg + (size_t)n0 * K + k0 };
#pragma unroll
        for (int mmat = 0; mmat < 2; mmat++) {
            const uint32_t mb = stg + mmat * MAT_BYTES;
#pragma unroll
            for (int j = 0; j < 4; j++) {
                const int q = t + j * 128;
                const int r = q >> 2, cq = q & 3;
                CPA16(mb + r * PITCH + cq * 16, gp[mmat] + (size_t)r * K + cq * 8);
            }
        }
    };

    const uint32_t a_row  = m_warp + (lane & 15);
    const uint32_t a_byte = ((lane >> 4) & 1) * 16;
    const uint32_t b_row  = n_warp + ((lane >> 4) & 1) * 8 + (lane & 7);
    const uint32_t b_byte = ((lane >> 3) & 1) * 16;

    load_chunk(0, 0);
    CPA_COMMIT();
    CPA_WAIT0();
    __syncthreads();

    for (int c = 0; c < NCHUNK; c++) {
        const int s = c & 1;
        if (c + 1 < NCHUNK) { load_chunk(c + 1, s ^ 1); CPA_COMMIT(); }

        const uint32_t stg = sb + s * STAGE_BYTES;
        const uint32_t Am = stg, Bm = stg + MAT_BYTES;

#pragma unroll
        for (int ks = 0; ks < 2; ks++) {
            const uint32_t koff = ks * 32;
            uint32_t af[4][4];
#pragma unroll
            for (int mt = 0; mt < 4; mt++)
                LDM4(af[mt], Am + (a_row + mt * 16) * PITCH + koff + a_byte);
#pragma unroll
            for (int p = 0; p < 4; p++) {
                uint32_t bf[4];
                LDM4(bf, Bm + (b_row + p * 16) * PITCH + koff + b_byte);
#pragma unroll
                for (int mt = 0; mt < 4; mt++) {
                    MMA_F16(acc[mt][2 * p],     af[mt], bf[0], bf[1]);
                    MMA_F16(acc[mt][2 * p + 1], af[mt], bf[2], bf[3]);
                }
            }
        }
        if (c + 1 < NCHUNK) CPA_WAIT0();
        __syncthreads();
    }

    // ---- epilogue ----
    const int lr = lane >> 2;
    const int lc = (lane & 3) * 2;
    const float rscale = 0.08838834764831845f;   // 1/sqrt(128)

#pragma unroll
    for (int mt = 0; mt < 4; mt++) {
#pragma unroll
        for (int nt = 0; nt < 8; nt++) {
            const int ncol = n_warp + nt * 8 + lc;
            const float b0 = bias[n0 + ncol];
            const float b1 = bias[n0 + ncol + 1];
#pragma unroll
            for (int half = 0; half < 2; half++) {
                const int m = m0 + m_warp + mt * 16 + lr + half * 8;
                float v0 = acc[mt][nt][half * 2 + 0] + b0;
                float v1 = acc[mt][nt][half * 2 + 1] + b1;
                if (MODE == 0) {
                    *(float2*)&out0[(size_t)m * N + n0 + ncol] = make_float2(v0, v1);
                } else {
                    const int part = n0 >> 11;           // 0=q, 1=k, 2=v
                    const int hh   = (n0 & 2047) >> 7;
                    const int bb   = m >> 11;
                    const int ss   = m & 2047;
                    if (part < 2) {
                        const float cs0 = cosT[ss * Dd + ncol];
                        const float sn0 = sinT[ss * Dd + ncol];
                        const float cs1 = cosT[ss * Dd + ncol + 1];
                        const float sn1 = sinT[ss * Dd + ncol + 1];
                        const float e = v0, o = v1;
                        v0 = e * cs0 - o * sn0;
                        v1 = o * cs1 + e * sn1;
                    }
                    size_t idx = ((((size_t)bb * Hh + hh) * Ss) + ss) * Dd + ncol;
                    if (part == 0) {
                        float s0 = v0 * rscale, s1 = v1 * rscale;
                        uint32_t ph = pack_rn(s0, s1);
                        uint32_t pl = pack_rn(s0 - bf_lo(ph), s1 - bf_hi(ph));
                        *(uint32_t*)(qhp + idx) = ph;
                        *(uint32_t*)(qlp + idx) = pl;
                    } else if (part == 1) {
                        *(float2*)&out1[idx] = make_float2(v0, v1);
                        uint32_t ph = pack_rn(v0, v1);
                        uint32_t pl = pack_rn(v0 - bf_lo(ph), v1 - bf_hi(ph));
                        *(uint32_t*)(khp + idx) = ph;
                        *(uint32_t*)(klp + idx) = pl;
                    } else {
                        *(float2*)&out2[idx] = make_float2(v0, v1);
                        *(uint32_t*)(vfp + idx) = pack_h2(v0, v1);
                    }
                }
            }
        }
    }
}

// ---------------------------------------------------------------------------
// Tensor-core flash attention: QK^T bf16 hi/lo 3-pass (score precision),
// P·V fp16 single-pass. CTA = 128 q-rows of one (b,h); 8 warps x 16 rows;
// BK=64; D=128. K hi/lo + V fp16 double-buffered via cp.async.
// ---------------------------------------------------------------------------
#define AT_PITCH 272                 // 128 elems = 256B + 16B pad
#define AT_QBYTES (128 * AT_PITCH)   // 34816
#define AT_KBYTES (64 * AT_PITCH)    // 17408
#define AT_STAGE  (3 * AT_KBYTES)    // Kh, Kl, Vf = 52224
#define AT_SMEM   (2 * AT_QBYTES + 2 * AT_STAGE)   // 174080

__global__ void __launch_bounds__(256, 1)
mha_attn_mma(const __nv_bfloat16* __restrict__ qh, const __nv_bfloat16* __restrict__ ql,
             const __nv_bfloat16* __restrict__ kh, const __nv_bfloat16* __restrict__ kl,
             const __half* __restrict__ vf,
             __half* __restrict__ yf)
{
    extern __shared__ char sm[];
    const uint32_t sb = smem_u32(sm);
    const int t = threadIdx.x, lane = t & 31, w = t >> 5;
    const int q0 = blockIdx.x * 128;
    const int h  = blockIdx.y, b = blockIdx.z;
    const size_t base = ((size_t)b * Hh + h) * (size_t)Ss * Dd;

    const uint32_t QH = sb, QL = sb + AT_QBYTES;
    const uint32_t ST0 = sb + 2 * AT_QBYTES;

    // ---- load Q hi/lo (128 rows x 256B each) ----
    {
        const __nv_bfloat16* sq[2] = { qh + base + (size_t)q0 * Dd,
                                       ql + base + (size_t)q0 * Dd };
#pragma unroll
        for (int mmat = 0; mmat < 2; mmat++) {
            const uint32_t dstb = mmat ? QL : QH;
#pragma unroll
            for (int j = 0; j < 8; j++) {
                int idx = t + j * 256;               // 2048 16B-chunks
                int r = idx >> 4, c = idx & 15;
                CPA16(dstb + r * AT_PITCH + c * 16, sq[mmat] + (size_t)r * Dd + c * 8);
            }
        }
    }

    auto load_kv = [&](int kt, int s) {
        const size_t off = base + (size_t)kt * 64 * Dd;
        const uint32_t stb = ST0 + s * AT_STAGE;
        const __nv_bfloat16* kb[2] = { kh + off, kl + off };
#pragma unroll
        for (int mmat = 0; mmat < 2; mmat++)
#pragma unroll
            for (int j = 0; j < 4; j++) {
                int idx = t + j * 256;               // 1024 chunks per matrix
                int r = idx >> 4, c = idx & 15;
                CPA16(stb + mmat * AT_KBYTES + r * AT_PITCH + c * 16,
                      kb[mmat] + (size_t)r * Dd + c * 8);
            }
        const __half* vb = vf + off;
#pragma unroll
        for (int j = 0; j < 4; j++) {
            int idx = t + j * 256;
            int r = idx >> 4, c = idx & 15;
            CPA16(stb + 2 * AT_KBYTES + r * AT_PITCH + c * 16, vb + (size_t)r * Dd + c * 8);
        }
    };

    load_kv(0, 0);
    CPA_COMMIT();
    CPA_WAIT0();
    __syncthreads();

    const int lr = lane >> 2, lcq = lane & 3;
    // ldmatrix address components
    const uint32_t qrow_off = (uint32_t)(w * 16 + (lane & 15)) * AT_PITCH + ((lane >> 4) & 1) * 16;
    const uint32_t krow_off = (uint32_t)(((lane >> 4) & 1) * 8 + (lane & 7)) * AT_PITCH + ((lane >> 3) & 1) * 16;
    const uint32_t vrow_off = (uint32_t)(lane & 15) * AT_PITCH + ((lane >> 4) & 1) * 16;

    float o[16][4];
#pragma unroll
    for (int i = 0; i < 16; i++)
#pragma unroll
        for (int j = 0; j < 4; j++) o[i][j] = 0.f;
    float mrow[2] = { -1e30f, -1e30f };
    float lrow[2] = { 0.f, 0.f };

    for (int kt = 0; kt < Ss / 64; kt++) {
        const int s = kt & 1;
        if (kt + 1 < Ss / 64) { load_kv(kt + 1, s ^ 1); CPA_COMMIT(); }

        const uint32_t KHs = ST0 + s * AT_STAGE;
        const uint32_t KLs = KHs + AT_KBYTES;
        const uint32_t VFs = KHs + 2 * AT_KBYTES;

        // ---- S = Q K^T (hi/lo 3-pass), warp tile 16x64 ----
        float sc[8][4];
#pragma unroll
        for (int i = 0; i < 8; i++)
#pragma unroll
            for (int j = 0; j < 4; j++) sc[i][j] = 0.f;

#pragma unroll
        for (int ks = 0; ks < 8; ks++) {
            uint32_t ahf[4], alf[4];
            LDM4(ahf, QH + qrow_off + ks * 32);
            LDM4(alf, QL + qrow_off + ks * 32);
#pragma unroll
            for (int ntp = 0; ntp < 4; ntp++) {
                uint32_t bhf[4], blf[4];
                LDM4(bhf, KHs + ntp * 16 * AT_PITCH + krow_off + ks * 32);
                LDM4(blf, KLs + ntp * 16 * AT_PITCH + krow_off + ks * 32);
                MMA_BF16(sc[2 * ntp],     ahf, bhf[0], bhf[1]);
                MMA_BF16(sc[2 * ntp + 1], ahf, bhf[2], bhf[3]);
                MMA_BF16(sc[2 * ntp],     ahf, blf[0], blf[1]);
                MMA_BF16(sc[2 * ntp + 1], ahf, blf[2], blf[3]);
                MMA_BF16(sc[2 * ntp],     alf, bhf[0], bhf[1]);
                MMA_BF16(sc[2 * ntp + 1], alf, bhf[2], bhf[3]);
            }
        }

        // ---- online softmax (rows lr and lr+8; quad-local reductions) ----
#pragma unroll
        for (int r = 0; r < 2; r++) {
            float mx = -1e30f;
#pragma unroll
            for (int nt = 0; nt < 8; nt++)
                mx = fmaxf(mx, fmaxf(sc[nt][2 * r], sc[nt][2 * r + 1]));
            mx = fmaxf(mx, __shfl_xor_sync(0xffffffffu, mx, 1));
            mx = fmaxf(mx, __shfl_xor_sync(0xffffffffu, mx, 2));
            const float mn = fmaxf(mrow[r], mx);
            const float al = __expf(mrow[r] - mn);
            mrow[r] = mn;
            float rs = 0.f;
#pragma unroll
            for (int nt = 0; nt < 8; nt++) {
                float p0 = __expf(sc[nt][2 * r]     - mn);
                float p1 = __expf(sc[nt][2 * r + 1] - mn);
                sc[nt][2 * r] = p0; sc[nt][2 * r + 1] = p1;
                rs += p0 + p1;
            }
            rs += __shfl_xor_sync(0xffffffffu, rs, 1);
            rs += __shfl_xor_sync(0xffffffffu, rs, 2);
            lrow[r] = lrow[r] * al + rs;
#pragma unroll
            for (int nt = 0; nt < 16; nt++) {
                o[nt][2 * r] *= al; o[nt][2 * r + 1] *= al;
            }
        }

        // ---- O += P V (fp16 single-pass); P A-frags straight from sc regs ----
#pragma unroll
        for (int kg = 0; kg < 4; kg++) {
            uint32_t af[4];
#pragma unroll
            for (int u = 0; u < 2; u++) {          // u=0: ntile 2kg, u=1: ntile 2kg+1
                af[2 * u]     = pack_h2(sc[2 * kg + u][0], sc[2 * kg + u][1]);
                af[2 * u + 1] = pack_h2(sc[2 * kg + u][2], sc[2 * kg + u][3]);
            }
#pragma unroll
            for (int dg = 0; dg < 8; dg++) {
                uint32_t bv[4];
                LDM4T(bv, VFs + kg * 16 * AT_PITCH + vrow_off + dg * 32);
                MMA_F16(o[2 * dg],     af, bv[0], bv[1]);
                MMA_F16(o[2 * dg + 1], af, bv[2], bv[3]);
            }
        }

        CPA_WAIT0();
        __syncthreads();
    }

    // ---- epilogue: scale by 1/l, emit fp16 y in (B,S,E) ----
    const float inv0 = 1.f / lrow[0];
    const float inv1 = 1.f / lrow[1];
    const int row0 = q0 + w * 16 + lr;
    const int row1 = row0 + 8;
#pragma unroll
    for (int nt = 0; nt < 16; nt++) {
        const int col = h * Dd + nt * 8 + 2 * lcq;
        {
            size_t idx = ((size_t)b * Ss + row0) * Ee + col;
            *(__half2*)(yf + idx) = __floats2half2_rn(o[nt][0] * inv0, o[nt][1] * inv0);
        }
        {
            size_t idx = ((size_t)b * Ss + row1) * Ee + col;
            *(__half2*)(yf + idx) = __floats2half2_rn(o[nt][2] * inv1, o[nt][3] * inv1);
        }
    }
}

// ---------------------------------------------------------------------------
extern "C" void kernel_launch(void* const* d_in, const int* in_sizes, int n_in,
                              void* d_out, int out_size)
{
    const float* x     = (const float*)d_in[0];
    const float* cosT  = (const float*)d_in[1];
    const float* sinT  = (const float*)d_in[2];
    const float* Wqkv  = (const float*)d_in[3];
    const float* bqkv  = (const float*)d_in[4];
    const float* Wproj = (const float*)d_in[5];
    const float* bproj = (const float*)d_in[6];

    float* out  = (float*)d_out;                 // (B,S,E)
    float* kout = out + HEAD_ELEMS;              // (B,H,S,D)
    float* vout = out + 2 * HEAD_ELEMS;          // (B,H,S,D)

    __half *xf, *wqf, *wpf, *yf, *vfp;
    __nv_bfloat16 *qhp, *qlp, *khp, *klp;
    cudaGetSymbolAddress((void**)&xf,  g_xf);
    cudaGetSymbolAddress((void**)&wqf, g_wqkvf);
    cudaGetSymbolAddress((void**)&wpf, g_wprojf);
    cudaGetSymbolAddress((void**)&yf,  g_yf);
    cudaGetSymbolAddress((void**)&qhp, g_qh);
    cudaGetSymbolAddress((void**)&qlp, g_ql);
    cudaGetSymbolAddress((void**)&khp, g_kh);
    cudaGetSymbolAddress((void**)&klp, g_kl);
    cudaGetSymbolAddress((void**)&vfp, g_vf);

    // 0) conversions: x -> fp16, weights -> transposed fp16
    {
        const int n4 = (Mm * Ee) / 4;
        conv_half<<<(n4 + 255) / 256, 256>>>((const float4*)x, (__half2*)xf, n4);
        transpose_half<<<dim3(N_QKV / 32, Ee / 32), 256>>>(Wqkv, wqf, Ee, N_QKV);
        transpose_half<<<dim3(Ee / 32, Ee / 32), 256>>>(Wproj, wpf, Ee, Ee);
    }

    // 1) QKV GEMM (fp16 single-pass, 64x64 warp tiles) + bias + RoPE
    {
        cudaFuncSetAttribute(gemm_mma<1>, cudaFuncAttributeMaxDynamicSharedMemorySize, GEMM_SMEM);
        dim3 grid(N_QKV / 128, Mm / 128);
        gemm_mma<1><<<grid, 128, GEMM_SMEM>>>(xf, wqf, bqkv, cosT, sinT,
                                              nullptr, kout, vout,
                                              qhp, qlp, khp, klp, vfp, Ee, N_QKV);
    }

    // 2) Flash attention: QK bf16 3-pass, PV fp16 single-pass -> fp16 y
    {
        cudaFuncSetAttribute(mha_attn_mma, cudaFuncAttributeMaxDynamicSharedMemorySize, AT_SMEM);
        dim3 grid(Ss / 128, Hh, Bb);
        mha_attn_mma<<<grid, 256, AT_SMEM>>>(qhp, qlp, khp, klp, vfp, yf);
    }

    // 3) Projection GEMM (fp16 single-pass, 64x64 warp tiles) + bias
    {
        cudaFuncSetAttribute(gemm_mma<0>, cudaFuncAttributeMaxDynamicSharedMemorySize, GEMM_SMEM);
        dim3 grid(Ee / 128, Mm / 128);
        gemm_mma<0><<<grid, 128, GEMM_SMEM>>>(yf, wpf, bproj, nullptr, nullptr,
                                              out, nullptr, nullptr,
                                              nullptr, nullptr, nullptr, nullptr,
                                              nullptr, Ee, Ee);
    }
}

// round 15
// speedup vs baseline: 2.4898x; 1.1933x over previous
#include <cuda_runtime.h>
#include <cuda_bf16.h>
#include <cuda_fp16.h>
#include <cstdint>

// Problem constants
#define Bb 4
#define Ss 2048
#define Ee 2048
#define Hh 16
#define Dd 128
#define Mm (Bb * Ss)          // 8192
#define N_QKV (3 * Ee)        // 6144
#define HEAD_ELEMS ((size_t)Bb * Hh * Ss * Dd)   // 16,777,216

// ---------------------------------------------------------------------------
// Scratch (device globals; no allocation allowed)
// ---------------------------------------------------------------------------
__device__ __half g_qf[HEAD_ELEMS];                              // q fp16 (B,H,S,D), pre-scaled
__device__ __half g_kf[HEAD_ELEMS];                              // k fp16
__device__ __half g_vf[HEAD_ELEMS];                              // v fp16
__device__ __half g_xf[(size_t)Mm * Ee];                         // x fp16
__device__ __half g_wqkvf[(size_t)N_QKV * Ee];                   // Wqkv^T fp16 [N,K]
__device__ __half g_wprojf[(size_t)Ee * Ee];                     // Wproj^T fp16 [N,K]
__device__ __half g_yf[(size_t)Mm * Ee];                         // attn out fp16 (B,S,E)

// ---------------------------------------------------------------------------
// PTX helpers (sm_80-era: mma.sync / ldmatrix / cp.async — legal on sm_103 base)
// ---------------------------------------------------------------------------
__device__ __forceinline__ uint32_t smem_u32(const void* p) {
    uint32_t a;
    asm("{ .reg .u64 t; cvta.to.shared.u64 t, %1; cvt.u32.u64 %0, t; }" : "=r"(a) : "l"(p));
    return a;
}

#define LDM4(r, addr)                                                          \
    asm volatile("ldmatrix.sync.aligned.m8n8.x4.shared.b16 {%0,%1,%2,%3}, [%4];" \
                 : "=r"((r)[0]), "=r"((r)[1]), "=r"((r)[2]), "=r"((r)[3])      \
                 : "r"(addr))

#define LDM4T(r, addr)                                                         \
    asm volatile("ldmatrix.sync.aligned.m8n8.x4.trans.shared.b16 {%0,%1,%2,%3}, [%4];" \
                 : "=r"((r)[0]), "=r"((r)[1]), "=r"((r)[2]), "=r"((r)[3])      \
                 : "r"(addr))

#define MMA_F16(d, a, b0, b1)                                                  \
    asm volatile("mma.sync.aligned.m16n8k16.row.col.f32.f16.f16.f32 "          \
                 "{%0,%1,%2,%3}, {%4,%5,%6,%7}, {%8,%9}, {%0,%1,%2,%3};"       \
                 : "+f"((d)[0]), "+f"((d)[1]), "+f"((d)[2]), "+f"((d)[3])      \
                 : "r"((a)[0]), "r"((a)[1]), "r"((a)[2]), "r"((a)[3]),         \
                   "r"(b0), "r"(b1))

#define CPA16(dst, src)                                                        \
    asm volatile("cp.async.cg.shared.global [%0], [%1], 16;"                   \
                 :: "r"(dst), "l"(src) : "memory")
#define CPA_COMMIT() asm volatile("cp.async.commit_group;" ::: "memory")
#define CPA_WAIT0()  asm volatile("cp.async.wait_group 0;" ::: "memory")

// pack two fp32 -> fp16x2
__device__ __forceinline__ uint32_t pack_h2(float lo, float hi) {
    __half2 h = __floats2half2_rn(lo, hi);
    return *(uint32_t*)&h;
}

// ---------------------------------------------------------------------------
// Conversion kernels
// ---------------------------------------------------------------------------
__global__ void __launch_bounds__(256)
conv_half(const float4* __restrict__ in, __half2* __restrict__ o, int n4)
{
    int i = blockIdx.x * 256 + threadIdx.x;
    if (i >= n4) return;
    float4 v = in[i];
    o[2 * i]     = __floats2half2_rn(v.x, v.y);
    o[2 * i + 1] = __floats2half2_rn(v.z, v.w);
}

// W [K,N] fp32 -> out [N,K] fp16
__global__ void __launch_bounds__(256)
transpose_half(const float* __restrict__ W, __half* __restrict__ th, int K, int N)
{
    __shared__ float tile[32][33];
    const int n0 = blockIdx.x * 32, k0 = blockIdx.y * 32;
    const int tx = threadIdx.x & 31, ty = threadIdx.x >> 5;
#pragma unroll
    for (int r = ty; r < 32; r += 8)
        tile[r][tx] = W[(size_t)(k0 + r) * N + n0 + tx];
    __syncthreads();
#pragma unroll
    for (int r = ty; r < 32; r += 8)
        th[(size_t)(n0 + r) * K + k0 + tx] = __float2half_rn(tile[tx][r]);
}

// ---------------------------------------------------------------------------
// mma.sync fp16 single-pass GEMM: C[M,N] = A[M,K] * B^T (B stored [N,K]),
// fp32 accum. CTA tile 128x128, 4 warps (2x2), warp tile 64x64, K chunks
// of 32, cp.async double-buffered smem (40KB), 80B row pitch.
// MODE 0: out0 = C + bias (proj).
// MODE 1: QKV epilogue — bias, RoPE, q*scale -> fp16; k -> fp32 + fp16;
//         v -> fp32 + fp16.
// ---------------------------------------------------------------------------
#define PITCH 80                       // bytes per 32-elem fp16 row (64B + 16B pad)
#define MAT_BYTES (128 * PITCH)        // 10240
#define STAGE_BYTES (2 * MAT_BYTES)    // A, B = 20480
#define GEMM_SMEM (2 * STAGE_BYTES)    // 40960

template <int MODE>
__global__ void __launch_bounds__(128, 2)
gemm_mma(const __half* __restrict__ Ag, const __half* __restrict__ Bg,
         const float* __restrict__ bias,
         const float* __restrict__ cosT, const float* __restrict__ sinT,
         float* __restrict__ out0, float* __restrict__ out1, float* __restrict__ out2,
         __half* __restrict__ qfp, __half* __restrict__ kfp, __half* __restrict__ vfp,
         int K, int N)
{
    extern __shared__ char sm[];
    const uint32_t sb = smem_u32(sm);
    const int t    = threadIdx.x;
    const int lane = t & 31;
    const int wid  = t >> 5;                 // 0..3
    const int m0   = blockIdx.y * 128;
    const int n0   = blockIdx.x * 128;
    const int m_warp = (wid & 1) * 64;
    const int n_warp = (wid >> 1) * 64;

    float acc[4][8][4];
#pragma unroll
    for (int i = 0; i < 4; i++)
#pragma unroll
        for (int j = 0; j < 8; j++)
#pragma unroll
            for (int k = 0; k < 4; k++) acc[i][j][k] = 0.f;

    const int NCHUNK = K / 32;

    // each matrix: 128 rows x 4 quads = 512 quads; 128 threads -> 4 per thread
    auto load_chunk = [&](int c, int s) {
        const uint32_t stg = sb + s * STAGE_BYTES;
        const int k0 = c * 32;
        const __half* gp[2] = { Ag + (size_t)m0 * K + k0, Bg + (size_t)n0 * K + k0 };
#pragma unroll
        for (int mmat = 0; mmat < 2; mmat++) {
            const uint32_t mb = stg + mmat * MAT_BYTES;
#pragma unroll
            for (int j = 0; j < 4; j++) {
                const int q = t + j * 128;
                const int r = q >> 2, cq = q & 3;
                CPA16(mb + r * PITCH + cq * 16, gp[mmat] + (size_t)r * K + cq * 8);
            }
        }
    };

    const uint32_t a_row  = m_warp + (lane & 15);
    const uint32_t a_byte = ((lane >> 4) & 1) * 16;
    const uint32_t b_row  = n_warp + ((lane >> 4) & 1) * 8 + (lane & 7);
    const uint32_t b_byte = ((lane >> 3) & 1) * 16;

    load_chunk(0, 0);
    CPA_COMMIT();
    CPA_WAIT0();
    __syncthreads();

    for (int c = 0; c < NCHUNK; c++) {
        const int s = c & 1;
        if (c + 1 < NCHUNK) { load_chunk(c + 1, s ^ 1); CPA_COMMIT(); }

        const uint32_t stg = sb + s * STAGE_BYTES;
        const uint32_t Am = stg, Bm = stg + MAT_BYTES;

#pragma unroll
        for (int ks = 0; ks < 2; ks++) {
            const uint32_t koff = ks * 32;
            uint32_t af[4][4];
#pragma unroll
            for (int mt = 0; mt < 4; mt++)
                LDM4(af[mt], Am + (a_row + mt * 16) * PITCH + koff + a_byte);
#pragma unroll
            for (int p = 0; p < 4; p++) {
                uint32_t bf[4];
                LDM4(bf, Bm + (b_row + p * 16) * PITCH + koff + b_byte);
#pragma unroll
                for (int mt = 0; mt < 4; mt++) {
                    MMA_F16(acc[mt][2 * p],     af[mt], bf[0], bf[1]);
                    MMA_F16(acc[mt][2 * p + 1], af[mt], bf[2], bf[3]);
                }
            }
        }
        if (c + 1 < NCHUNK) CPA_WAIT0();
        __syncthreads();
    }

    // ---- epilogue ----
    const int lr = lane >> 2;
    const int lc = (lane & 3) * 2;
    const float rscale = 0.08838834764831845f;   // 1/sqrt(128)

#pragma unroll
    for (int mt = 0; mt < 4; mt++) {
#pragma unroll
        for (int nt = 0; nt < 8; nt++) {
            const int ncol = n_warp + nt * 8 + lc;
            const float b0 = bias[n0 + ncol];
            const float b1 = bias[n0 + ncol + 1];
#pragma unroll
            for (int half = 0; half < 2; half++) {
                const int m = m0 + m_warp + mt * 16 + lr + half * 8;
                float v0 = acc[mt][nt][half * 2 + 0] + b0;
                float v1 = acc[mt][nt][half * 2 + 1] + b1;
                if (MODE == 0) {
                    *(float2*)&out0[(size_t)m * N + n0 + ncol] = make_float2(v0, v1);
                } else {
                    const int part = n0 >> 11;           // 0=q, 1=k, 2=v
                    const int hh   = (n0 & 2047) >> 7;
                    const int bb   = m >> 11;
                    const int ss   = m & 2047;
                    if (part < 2) {
                        const float cs0 = cosT[ss * Dd + ncol];
                        const float sn0 = sinT[ss * Dd + ncol];
                        const float cs1 = cosT[ss * Dd + ncol + 1];
                        const float sn1 = sinT[ss * Dd + ncol + 1];
                        const float e = v0, o = v1;
                        v0 = e * cs0 - o * sn0;
                        v1 = o * cs1 + e * sn1;
                    }
                    size_t idx = ((((size_t)bb * Hh + hh) * Ss) + ss) * Dd + ncol;
                    if (part == 0) {
                        *(uint32_t*)(qfp + idx) = pack_h2(v0 * rscale, v1 * rscale);
                    } else if (part == 1) {
                        *(float2*)&out1[idx] = make_float2(v0, v1);
                        *(uint32_t*)(kfp + idx) = pack_h2(v0, v1);
                    } else {
                        *(float2*)&out2[idx] = make_float2(v0, v1);
                        *(uint32_t*)(vfp + idx) = pack_h2(v0, v1);
                    }
                }
            }
        }
    }
}

// ---------------------------------------------------------------------------
// Tensor-core flash attention, all-fp16 operands (fp32 accum + softmax):
// QK^T fp16 single-pass, P·V fp16 single-pass.
// CTA = 128 q-rows of one (b,h); 8 warps x 16 rows; BK=64; D=128.
// K + V fp16 double-buffered via cp.async; V via ldmatrix.trans.
// ---------------------------------------------------------------------------
#define AT_PITCH 272                 // 128 elems = 256B + 16B pad
#define AT_QBYTES (128 * AT_PITCH)   // 34816
#define AT_KBYTES (64 * AT_PITCH)    // 17408
#define AT_STAGE  (2 * AT_KBYTES)    // Kf, Vf = 34816
#define AT_SMEM   (AT_QBYTES + 2 * AT_STAGE)   // 104448

__global__ void __launch_bounds__(256, 1)
mha_attn_mma(const __half* __restrict__ qf, const __half* __restrict__ kf,
             const __half* __restrict__ vf,
             __half* __restrict__ yf)
{
    extern __shared__ char sm[];
    const uint32_t sb = smem_u32(sm);
    const int t = threadIdx.x, lane = t & 31, w = t >> 5;
    const int q0 = blockIdx.x * 128;
    const int h  = blockIdx.y, b = blockIdx.z;
    const size_t base = ((size_t)b * Hh + h) * (size_t)Ss * Dd;

    const uint32_t QF = sb;
    const uint32_t ST0 = sb + AT_QBYTES;

    // ---- load Q fp16 (128 rows x 256B) ----
    {
        const __half* sq = qf + base + (size_t)q0 * Dd;
#pragma unroll
        for (int j = 0; j < 8; j++) {
            int idx = t + j * 256;               // 2048 16B-chunks
            int r = idx >> 4, c = idx & 15;
            CPA16(QF + r * AT_PITCH + c * 16, sq + (size_t)r * Dd + c * 8);
        }
    }

    auto load_kv = [&](int kt, int s) {
        const size_t off = base + (size_t)kt * 64 * Dd;
        const uint32_t stb = ST0 + s * AT_STAGE;
        const __half* srcs[2] = { kf + off, vf + off };
#pragma unroll
        for (int mmat = 0; mmat < 2; mmat++)
#pragma unroll
            for (int j = 0; j < 4; j++) {
                int idx = t + j * 256;               // 1024 chunks per matrix
                int r = idx >> 4, c = idx & 15;
                CPA16(stb + mmat * AT_KBYTES + r * AT_PITCH + c * 16,
                      srcs[mmat] + (size_t)r * Dd + c * 8);
            }
    };

    load_kv(0, 0);
    CPA_COMMIT();
    CPA_WAIT0();
    __syncthreads();

    const int lr = lane >> 2, lcq = lane & 3;
    // ldmatrix address components
    const uint32_t qrow_off = (uint32_t)(w * 16 + (lane & 15)) * AT_PITCH + ((lane >> 4) & 1) * 16;
    const uint32_t krow_off = (uint32_t)(((lane >> 4) & 1) * 8 + (lane & 7)) * AT_PITCH + ((lane >> 3) & 1) * 16;
    const uint32_t vrow_off = (uint32_t)(lane & 15) * AT_PITCH + ((lane >> 4) & 1) * 16;

    float o[16][4];
#pragma unroll
    for (int i = 0; i < 16; i++)
#pragma unroll
        for (int j = 0; j < 4; j++) o[i][j] = 0.f;
    float mrow[2] = { -1e30f, -1e30f };
    float lrow[2] = { 0.f, 0.f };

    for (int kt = 0; kt < Ss / 64; kt++) {
        const int s = kt & 1;
        if (kt + 1 < Ss / 64) { load_kv(kt + 1, s ^ 1); CPA_COMMIT(); }

        const uint32_t KFs = ST0 + s * AT_STAGE;
        const uint32_t VFs = KFs + AT_KBYTES;

        // ---- S = Q K^T (fp16 single-pass), warp tile 16x64 ----
        float sc[8][4];
#pragma unroll
        for (int i = 0; i < 8; i++)
#pragma unroll
            for (int j = 0; j < 4; j++) sc[i][j] = 0.f;

#pragma unroll
        for (int ks = 0; ks < 8; ks++) {
            uint32_t aqf[4];
            LDM4(aqf, QF + qrow_off + ks * 32);
#pragma unroll
            for (int ntp = 0; ntp < 4; ntp++) {
                uint32_t bkf[4];
                LDM4(bkf, KFs + ntp * 16 * AT_PITCH + krow_off + ks * 32);
                MMA_F16(sc[2 * ntp],     aqf, bkf[0], bkf[1]);
                MMA_F16(sc[2 * ntp + 1], aqf, bkf[2], bkf[3]);
            }
        }

        // ---- online softmax (rows lr and lr+8; quad-local reductions) ----
#pragma unroll
        for (int r = 0; r < 2; r++) {
            float mx = -1e30f;
#pragma unroll
            for (int nt = 0; nt < 8; nt++)
                mx = fmaxf(mx, fmaxf(sc[nt][2 * r], sc[nt][2 * r + 1]));
            mx = fmaxf(mx, __shfl_xor_sync(0xffffffffu, mx, 1));
            mx = fmaxf(mx, __shfl_xor_sync(0xffffffffu, mx, 2));
            const float mn = fmaxf(mrow[r], mx);
            const float al = __expf(mrow[r] - mn);
            mrow[r] = mn;
            float rs = 0.f;
#pragma unroll
            for (int nt = 0; nt < 8; nt++) {
                float p0 = __expf(sc[nt][2 * r]     - mn);
                float p1 = __expf(sc[nt][2 * r + 1] - mn);
                sc[nt][2 * r] = p0; sc[nt][2 * r + 1] = p1;
                rs += p0 + p1;
            }
            rs += __shfl_xor_sync(0xffffffffu, rs, 1);
            rs += __shfl_xor_sync(0xffffffffu, rs, 2);
            lrow[r] = lrow[r] * al + rs;
#pragma unroll
            for (int nt = 0; nt < 16; nt++) {
                o[nt][2 * r] *= al; o[nt][2 * r + 1] *= al;
            }
        }

        // ---- O += P V (fp16 single-pass); P A-frags straight from sc regs ----
#pragma unroll
        for (int kg = 0; kg < 4; kg++) {
            uint32_t af[4];
#pragma unroll
            for (int u = 0; u < 2; u++) {          // u=0: ntile 2kg, u=1: ntile 2kg+1
                af[2 * u]     = pack_h2(sc[2 * kg + u][0], sc[2 * kg + u][1]);
                af[2 * u + 1] = pack_h2(sc[2 * kg + u][2], sc[2 * kg + u][3]);
            }
#pragma unroll
            for (int dg = 0; dg < 8; dg++) {
                uint32_t bv[4];
                LDM4T(bv, VFs + kg * 16 * AT_PITCH + vrow_off + dg * 32);
                MMA_F16(o[2 * dg],     af, bv[0], bv[1]);
                MMA_F16(o[2 * dg + 1], af, bv[2], bv[3]);
            }
        }

        CPA_WAIT0();
        __syncthreads();
    }

    // ---- epilogue: scale by 1/l, emit fp16 y in (B,S,E) ----
    const float inv0 = 1.f / lrow[0];
    const float inv1 = 1.f / lrow[1];
    const int row0 = q0 + w * 16 + lr;
    const int row1 = row0 + 8;
#pragma unroll
    for (int nt = 0; nt < 16; nt++) {
        const int col = h * Dd + nt * 8 + 2 * lcq;
        {
            size_t idx = ((size_t)b * Ss + row0) * Ee + col;
            *(__half2*)(yf + idx) = __floats2half2_rn(o[nt][0] * inv0, o[nt][1] * inv0);
        }
        {
            size_t idx = ((size_t)b * Ss + row1) * Ee + col;
            *(__half2*)(yf + idx) = __floats2half2_rn(o[nt][2] * inv1, o[nt][3] * inv1);
        }
    }
}

// ---------------------------------------------------------------------------
extern "C" void kernel_launch(void* const* d_in, const int* in_sizes, int n_in,
                              void* d_out, int out_size)
{
    const float* x     = (const float*)d_in[0];
    const float* cosT  = (const float*)d_in[1];
    const float* sinT  = (const float*)d_in[2];
    const float* Wqkv  = (const float*)d_in[3];
    const float* bqkv  = (const float*)d_in[4];
    const float* Wproj = (const float*)d_in[5];
    const float* bproj = (const float*)d_in[6];

    float* out  = (float*)d_out;                 // (B,S,E)
    float* kout = out + HEAD_ELEMS;              // (B,H,S,D)
    float* vout = out + 2 * HEAD_ELEMS;          // (B,H,S,D)

    __half *xf, *wqf, *wpf, *yf, *qfp, *kfp, *vfp;
    cudaGetSymbolAddress((void**)&xf,  g_xf);
    cudaGetSymbolAddress((void**)&wqf, g_wqkvf);
    cudaGetSymbolAddress((void**)&wpf, g_wprojf);
    cudaGetSymbolAddress((void**)&yf,  g_yf);
    cudaGetSymbolAddress((void**)&qfp, g_qf);
    cudaGetSymbolAddress((void**)&kfp, g_kf);
    cudaGetSymbolAddress((void**)&vfp, g_vf);

    // 0) conversions: x -> fp16, weights -> transposed fp16
    {
        const int n4 = (Mm * Ee) / 4;
        conv_half<<<(n4 + 255) / 256, 256>>>((const float4*)x, (__half2*)xf, n4);
        transpose_half<<<dim3(N_QKV / 32, Ee / 32), 256>>>(Wqkv, wqf, Ee, N_QKV);
        transpose_half<<<dim3(Ee / 32, Ee / 32), 256>>>(Wproj, wpf, Ee, Ee);
    }

    // 1) QKV GEMM (fp16 single-pass, 64x64 warp tiles) + bias + RoPE
    {
        cudaFuncSetAttribute(gemm_mma<1>, cudaFuncAttributeMaxDynamicSharedMemorySize, GEMM_SMEM);
        dim3 grid(N_QKV / 128, Mm / 128);
        gemm_mma<1><<<grid, 128, GEMM_SMEM>>>(xf, wqf, bqkv, cosT, sinT,
                                              nullptr, kout, vout,
                                              qfp, kfp, vfp, Ee, N_QKV);
    }

    // 2) Flash attention: QK fp16 1-pass, PV fp16 1-pass -> fp16 y
    {
        cudaFuncSetAttribute(mha_attn_mma, cudaFuncAttributeMaxDynamicSharedMemorySize, AT_SMEM);
        dim3 grid(Ss / 128, Hh, Bb);
        mha_attn_mma<<<grid, 256, AT_SMEM>>>(qfp, kfp, vfp, yf);
    }

    // 3) Projection GEMM (fp16 single-pass, 64x64 warp tiles) + bias
    {
        cudaFuncSetAttribute(gemm_mma<0>, cudaFuncAttributeMaxDynamicSharedMemorySize, GEMM_SMEM);
        dim3 grid(Ee / 128, Mm / 128);
        gemm_mma<0><<<grid, 128, GEMM_SMEM>>>(yf, wpf, bproj, nullptr, nullptr,
                                              out, nullptr, nullptr,
                                              nullptr, nullptr, nullptr, Ee, Ee);
    }
}

// round 16
// speedup vs baseline: 2.5146x; 1.0099x over previous
#include <cuda_runtime.h>
#include <cuda_bf16.h>
#include <cuda_fp16.h>
#include <cstdint>

// Problem constants
#define Bb 4
#define Ss 2048
#define Ee 2048
#define Hh 16
#define Dd 128
#define Mm (Bb * Ss)          // 8192
#define N_QKV (3 * Ee)        // 6144
#define HEAD_ELEMS ((size_t)Bb * Hh * Ss * Dd)   // 16,777,216

// ---------------------------------------------------------------------------
// Scratch (device globals; no allocation allowed)
// ---------------------------------------------------------------------------
__device__ __half g_qf[HEAD_ELEMS];                              // q fp16 (B,H,S,D), pre-scaled
__device__ __half g_kf[HEAD_ELEMS];                              // k fp16
__device__ __half g_vf[HEAD_ELEMS];                              // v fp16
__device__ __half g_xf[(size_t)Mm * Ee];                         // x fp16
__device__ __half g_wqkvf[(size_t)N_QKV * Ee];                   // Wqkv^T fp16 [N,K]
__device__ __half g_wprojf[(size_t)Ee * Ee];                     // Wproj^T fp16 [N,K]
__device__ __half g_yf[(size_t)Mm * Ee];                         // attn out fp16 (B,S,E)

// ---------------------------------------------------------------------------
// PTX helpers (sm_80-era: mma.sync / ldmatrix / cp.async — legal on sm_103 base)
// ---------------------------------------------------------------------------
__device__ __forceinline__ uint32_t smem_u32(const void* p) {
    uint32_t a;
    asm("{ .reg .u64 t; cvta.to.shared.u64 t, %1; cvt.u32.u64 %0, t; }" : "=r"(a) : "l"(p));
    return a;
}

#define LDM4(r, addr)                                                          \
    asm volatile("ldmatrix.sync.aligned.m8n8.x4.shared.b16 {%0,%1,%2,%3}, [%4];" \
                 : "=r"((r)[0]), "=r"((r)[1]), "=r"((r)[2]), "=r"((r)[3])      \
                 : "r"(addr))

#define LDM4T(r, addr)                                                         \
    asm volatile("ldmatrix.sync.aligned.m8n8.x4.trans.shared.b16 {%0,%1,%2,%3}, [%4];" \
                 : "=r"((r)[0]), "=r"((r)[1]), "=r"((r)[2]), "=r"((r)[3])      \
                 : "r"(addr))

#define MMA_F16(d, a, b0, b1)                                                  \
    asm volatile("mma.sync.aligned.m16n8k16.row.col.f32.f16.f16.f32 "          \
                 "{%0,%1,%2,%3}, {%4,%5,%6,%7}, {%8,%9}, {%0,%1,%2,%3};"       \
                 : "+f"((d)[0]), "+f"((d)[1]), "+f"((d)[2]), "+f"((d)[3])      \
                 : "r"((a)[0]), "r"((a)[1]), "r"((a)[2]), "r"((a)[3]),         \
                   "r"(b0), "r"(b1))

#define CPA16(dst, src)                                                        \
    asm volatile("cp.async.cg.shared.global [%0], [%1], 16;"                   \
                 :: "r"(dst), "l"(src) : "memory")
#define CPA_COMMIT() asm volatile("cp.async.commit_group;" ::: "memory")
#define CPA_WAIT0()  asm volatile("cp.async.wait_group 0;" ::: "memory")

// pack two fp32 -> fp16x2
__device__ __forceinline__ uint32_t pack_h2(float lo, float hi) {
    __half2 h = __floats2half2_rn(lo, hi);
    return *(uint32_t*)&h;
}

// ---------------------------------------------------------------------------
// Conversion kernels
// ---------------------------------------------------------------------------
__global__ void __launch_bounds__(256)
conv_half(const float4* __restrict__ in, __half2* __restrict__ o, int n4)
{
    int i = blockIdx.x * 256 + threadIdx.x;
    if (i >= n4) return;
    float4 v = in[i];
    o[2 * i]     = __floats2half2_rn(v.x, v.y);
    o[2 * i + 1] = __floats2half2_rn(v.z, v.w);
}

// W [K,N] fp32 -> out [N,K] fp16
__global__ void __launch_bounds__(256)
transpose_half(const float* __restrict__ W, __half* __restrict__ th, int K, int N)
{
    __shared__ float tile[32][33];
    const int n0 = blockIdx.x * 32, k0 = blockIdx.y * 32;
    const int tx = threadIdx.x & 31, ty = threadIdx.x >> 5;
#pragma unroll
    for (int r = ty; r < 32; r += 8)
        tile[r][tx] = W[(size_t)(k0 + r) * N + n0 + tx];
    __syncthreads();
#pragma unroll
    for (int r = ty; r < 32; r += 8)
        th[(size_t)(n0 + r) * K + k0 + tx] = __float2half_rn(tile[tx][r]);
}

// ---------------------------------------------------------------------------
// mma.sync fp16 single-pass GEMM: C[M,N] = A[M,K] * B^T (B stored [N,K]),
// fp32 accum. CTA tile 128x128, 4 warps (2x2), warp tile 64x64, K chunks
// of 64 (long phases, half the syncs), cp.async double-buffered smem
// (74KB -> 2 CTAs/SM), 144B row pitch (128B data + 16B pad; conflict-free:
// 16*r mod 128 cycles through all 8 16B bank positions per 8 rows).
// MODE 0: out0 = C + bias (proj).
// MODE 1: QKV epilogue — bias, RoPE, q*scale -> fp16; k,v -> fp32 + fp16.
// ---------------------------------------------------------------------------
#define PITCH 144                      // bytes per 64-elem fp16 row (128B + 16B pad)
#define MAT_BYTES (128 * PITCH)        // 18432
#define STAGE_BYTES (2 * MAT_BYTES)    // A, B = 36864
#define GEMM_SMEM (2 * STAGE_BYTES)    // 73728

template <int MODE>
__global__ void __launch_bounds__(128, 2)
gemm_mma(const __half* __restrict__ Ag, const __half* __restrict__ Bg,
         const float* __restrict__ bias,
         const float* __restrict__ cosT, const float* __restrict__ sinT,
         float* __restrict__ out0, float* __restrict__ out1, float* __restrict__ out2,
         __half* __restrict__ qfp, __half* __restrict__ kfp, __half* __restrict__ vfp,
         int K, int N)
{
    extern __shared__ char sm[];
    const uint32_t sb = smem_u32(sm);
    const int t    = threadIdx.x;
    const int lane = t & 31;
    const int wid  = t >> 5;                 // 0..3
    const int m0   = blockIdx.y * 128;
    const int n0   = blockIdx.x * 128;
    const int m_warp = (wid & 1) * 64;
    const int n_warp = (wid >> 1) * 64;

    float acc[4][8][4];
#pragma unroll
    for (int i = 0; i < 4; i++)
#pragma unroll
        for (int j = 0; j < 8; j++)
#pragma unroll
            for (int k = 0; k < 4; k++) acc[i][j][k] = 0.f;

    const int NCHUNK = K / 64;

    // each matrix: 128 rows x 8 quads(16B) = 1024 quads; 128 threads -> 8/thread
    auto load_chunk = [&](int c, int s) {
        const uint32_t stg = sb + s * STAGE_BYTES;
        const int k0 = c * 64;
        const __half* gp[2] = { Ag + (size_t)m0 * K + k0, Bg + (size_t)n0 * K + k0 };
#pragma unroll
        for (int mmat = 0; mmat < 2; mmat++) {
            const uint32_t mb = stg + mmat * MAT_BYTES;
#pragma unroll
            for (int j = 0; j < 8; j++) {
                const int q = t + j * 128;
                const int r = q >> 3, cq = q & 7;
                CPA16(mb + r * PITCH + cq * 16, gp[mmat] + (size_t)r * K + cq * 8);
            }
        }
    };

    const uint32_t a_row  = m_warp + (lane & 15);
    const uint32_t a_byte = ((lane >> 4) & 1) * 16;
    const uint32_t b_row  = n_warp + ((lane >> 4) & 1) * 8 + (lane & 7);
    const uint32_t b_byte = ((lane >> 3) & 1) * 16;

    load_chunk(0, 0);
    CPA_COMMIT();
    CPA_WAIT0();
    __syncthreads();

    for (int c = 0; c < NCHUNK; c++) {
        const int s = c & 1;
        if (c + 1 < NCHUNK) { load_chunk(c + 1, s ^ 1); CPA_COMMIT(); }

        const uint32_t stg = sb + s * STAGE_BYTES;
        const uint32_t Am = stg, Bm = stg + MAT_BYTES;

#pragma unroll
        for (int ks = 0; ks < 4; ks++) {
            const uint32_t koff = ks * 32;
            uint32_t af[4][4];
#pragma unroll
            for (int mt = 0; mt < 4; mt++)
                LDM4(af[mt], Am + (a_row + mt * 16) * PITCH + koff + a_byte);
#pragma unroll
            for (int p = 0; p < 4; p++) {
                uint32_t bf[4];
                LDM4(bf, Bm + (b_row + p * 16) * PITCH + koff + b_byte);
#pragma unroll
                for (int mt = 0; mt < 4; mt++) {
                    MMA_F16(acc[mt][2 * p],     af[mt], bf[0], bf[1]);
                    MMA_F16(acc[mt][2 * p + 1], af[mt], bf[2], bf[3]);
                }
            }
        }
        if (c + 1 < NCHUNK) CPA_WAIT0();
        __syncthreads();
    }

    // ---- epilogue ----
    const int lr = lane >> 2;
    const int lc = (lane & 3) * 2;
    const float rscale = 0.08838834764831845f;   // 1/sqrt(128)

#pragma unroll
    for (int mt = 0; mt < 4; mt++) {
#pragma unroll
        for (int nt = 0; nt < 8; nt++) {
            const int ncol = n_warp + nt * 8 + lc;
            const float b0 = bias[n0 + ncol];
            const float b1 = bias[n0 + ncol + 1];
#pragma unroll
            for (int half = 0; half < 2; half++) {
                const int m = m0 + m_warp + mt * 16 + lr + half * 8;
                float v0 = acc[mt][nt][half * 2 + 0] + b0;
                float v1 = acc[mt][nt][half * 2 + 1] + b1;
                if (MODE == 0) {
                    *(float2*)&out0[(size_t)m * N + n0 + ncol] = make_float2(v0, v1);
                } else {
                    const int part = n0 >> 11;           // 0=q, 1=k, 2=v
                    const int hh   = (n0 & 2047) >> 7;
                    const int bb   = m >> 11;
                    const int ss   = m & 2047;
                    if (part < 2) {
                        const float cs0 = cosT[ss * Dd + ncol];
                        const float sn0 = sinT[ss * Dd + ncol];
                        const float cs1 = cosT[ss * Dd + ncol + 1];
                        const float sn1 = sinT[ss * Dd + ncol + 1];
                        const float e = v0, o = v1;
                        v0 = e * cs0 - o * sn0;
                        v1 = o * cs1 + e * sn1;
                    }
                    size_t idx = ((((size_t)bb * Hh + hh) * Ss) + ss) * Dd + ncol;
                    if (part == 0) {
                        *(uint32_t*)(qfp + idx) = pack_h2(v0 * rscale, v1 * rscale);
                    } else if (part == 1) {
                        *(float2*)&out1[idx] = make_float2(v0, v1);
                        *(uint32_t*)(kfp + idx) = pack_h2(v0, v1);
                    } else {
                        *(float2*)&out2[idx] = make_float2(v0, v1);
                        *(uint32_t*)(vfp + idx) = pack_h2(v0, v1);
                    }
                }
            }
        }
    }
}

// ---------------------------------------------------------------------------
// Tensor-core flash attention, all-fp16 operands (fp32 accum + softmax):
// QK^T fp16 single-pass, P·V fp16 single-pass.
// CTA = 128 q-rows of one (b,h); 8 warps x 16 rows; BK=64; D=128.
// K + V fp16 double-buffered via cp.async; V via ldmatrix.trans.
// ---------------------------------------------------------------------------
#define AT_PITCH 272                 // 128 elems = 256B + 16B pad
#define AT_QBYTES (128 * AT_PITCH)   // 34816
#define AT_KBYTES (64 * AT_PITCH)    // 17408
#define AT_STAGE  (2 * AT_KBYTES)    // Kf, Vf = 34816
#define AT_SMEM   (AT_QBYTES + 2 * AT_STAGE)   // 104448

__global__ void __launch_bounds__(256, 1)
mha_attn_mma(const __half* __restrict__ qf, const __half* __restrict__ kf,
             const __half* __restrict__ vf,
             __half* __restrict__ yf)
{
    extern __shared__ char sm[];
    const uint32_t sb = smem_u32(sm);
    const int t = threadIdx.x, lane = t & 31, w = t >> 5;
    const int q0 = blockIdx.x * 128;
    const int h  = blockIdx.y, b = blockIdx.z;
    const size_t base = ((size_t)b * Hh + h) * (size_t)Ss * Dd;

    const uint32_t QF = sb;
    const uint32_t ST0 = sb + AT_QBYTES;

    // ---- load Q fp16 (128 rows x 256B) ----
    {
        const __half* sq = qf + base + (size_t)q0 * Dd;
#pragma unroll
        for (int j = 0; j < 8; j++) {
            int idx = t + j * 256;               // 2048 16B-chunks
            int r = idx >> 4, c = idx & 15;
            CPA16(QF + r * AT_PITCH + c * 16, sq + (size_t)r * Dd + c * 8);
        }
    }

    auto load_kv = [&](int kt, int s) {
        const size_t off = base + (size_t)kt * 64 * Dd;
        const uint32_t stb = ST0 + s * AT_STAGE;
        const __half* srcs[2] = { kf + off, vf + off };
#pragma unroll
        for (int mmat = 0; mmat < 2; mmat++)
#pragma unroll
            for (int j = 0; j < 4; j++) {
                int idx = t + j * 256;               // 1024 chunks per matrix
                int r = idx >> 4, c = idx & 15;
                CPA16(stb + mmat * AT_KBYTES + r * AT_PITCH + c * 16,
                      srcs[mmat] + (size_t)r * Dd + c * 8);
            }
    };

    load_kv(0, 0);
    CPA_COMMIT();
    CPA_WAIT0();
    __syncthreads();

    const int lr = lane >> 2, lcq = lane & 3;
    // ldmatrix address components
    const uint32_t qrow_off = (uint32_t)(w * 16 + (lane & 15)) * AT_PITCH + ((lane >> 4) & 1) * 16;
    const uint32_t krow_off = (uint32_t)(((lane >> 4) & 1) * 8 + (lane & 7)) * AT_PITCH + ((lane >> 3) & 1) * 16;
    const uint32_t vrow_off = (uint32_t)(lane & 15) * AT_PITCH + ((lane >> 4) & 1) * 16;

    float o[16][4];
#pragma unroll
    for (int i = 0; i < 16; i++)
#pragma unroll
        for (int j = 0; j < 4; j++) o[i][j] = 0.f;
    float mrow[2] = { -1e30f, -1e30f };
    float lrow[2] = { 0.f, 0.f };

    for (int kt = 0; kt < Ss / 64; kt++) {
        const int s = kt & 1;
        if (kt + 1 < Ss / 64) { load_kv(kt + 1, s ^ 1); CPA_COMMIT(); }

        const uint32_t KFs = ST0 + s * AT_STAGE;
        const uint32_t VFs = KFs + AT_KBYTES;

        // ---- S = Q K^T (fp16 single-pass), warp tile 16x64 ----
        float sc[8][4];
#pragma unroll
        for (int i = 0; i < 8; i++)
#pragma unroll
            for (int j = 0; j < 4; j++) sc[i][j] = 0.f;

#pragma unroll
        for (int ks = 0; ks < 8; ks++) {
            uint32_t aqf[4];
            LDM4(aqf, QF + qrow_off + ks * 32);
#pragma unroll
            for (int ntp = 0; ntp < 4; ntp++) {
                uint32_t bkf[4];
                LDM4(bkf, KFs + ntp * 16 * AT_PITCH + krow_off + ks * 32);
                MMA_F16(sc[2 * ntp],     aqf, bkf[0], bkf[1]);
                MMA_F16(sc[2 * ntp + 1], aqf, bkf[2], bkf[3]);
            }
        }

        // ---- online softmax (rows lr and lr+8; quad-local reductions) ----
#pragma unroll
        for (int r = 0; r < 2; r++) {
            float mx = -1e30f;
#pragma unroll
            for (int nt = 0; nt < 8; nt++)
                mx = fmaxf(mx, fmaxf(sc[nt][2 * r], sc[nt][2 * r + 1]));
            mx = fmaxf(mx, __shfl_xor_sync(0xffffffffu, mx, 1));
            mx = fmaxf(mx, __shfl_xor_sync(0xffffffffu, mx, 2));
            const float mn = fmaxf(mrow[r], mx);
            const float al = __expf(mrow[r] - mn);
            mrow[r] = mn;
            float rs = 0.f;
#pragma unroll
            for (int nt = 0; nt < 8; nt++) {
                float p0 = __expf(sc[nt][2 * r]     - mn);
                float p1 = __expf(sc[nt][2 * r + 1] - mn);
                sc[nt][2 * r] = p0; sc[nt][2 * r + 1] = p1;
                rs += p0 + p1;
            }
            rs += __shfl_xor_sync(0xffffffffu, rs, 1);
            rs += __shfl_xor_sync(0xffffffffu, rs, 2);
            lrow[r] = lrow[r] * al + rs;
#pragma unroll
            for (int nt = 0; nt < 16; nt++) {
                o[nt][2 * r] *= al; o[nt][2 * r + 1] *= al;
            }
        }

        // ---- O += P V (fp16 single-pass); P A-frags straight from sc regs ----
#pragma unroll
        for (int kg = 0; kg < 4; kg++) {
            uint32_t af[4];
#pragma unroll
            for (int u = 0; u < 2; u++) {          // u=0: ntile 2kg, u=1: ntile 2kg+1
                af[2 * u]     = pack_h2(sc[2 * kg + u][0], sc[2 * kg + u][1]);
                af[2 * u + 1] = pack_h2(sc[2 * kg + u][2], sc[2 * kg + u][3]);
            }
#pragma unroll
            for (int dg = 0; dg < 8; dg++) {
                uint32_t bv[4];
                LDM4T(bv, VFs + kg * 16 * AT_PITCH + vrow_off + dg * 32);
                MMA_F16(o[2 * dg],     af, bv[0], bv[1]);
                MMA_F16(o[2 * dg + 1], af, bv[2], bv[3]);
            }
        }

        CPA_WAIT0();
        __syncthreads();
    }

    // ---- epilogue: scale by 1/l, emit fp16 y in (B,S,E) ----
    const float inv0 = 1.f / lrow[0];
    const float inv1 = 1.f / lrow[1];
    const int row0 = q0 + w * 16 + lr;
    const int row1 = row0 + 8;
#pragma unroll
    for (int nt = 0; nt < 16; nt++) {
        const int col = h * Dd + nt * 8 + 2 * lcq;
        {
            size_t idx = ((size_t)b * Ss + row0) * Ee + col;
            *(__half2*)(yf + idx) = __floats2half2_rn(o[nt][0] * inv0, o[nt][1] * inv0);
        }
        {
            size_t idx = ((size_t)b * Ss + row1) * Ee + col;
            *(__half2*)(yf + idx) = __floats2half2_rn(o[nt][2] * inv1, o[nt][3] * inv1);
        }
    }
}

// ---------------------------------------------------------------------------
extern "C" void kernel_launch(void* const* d_in, const int* in_sizes, int n_in,
                              void* d_out, int out_size)
{
    const float* x     = (const float*)d_in[0];
    const float* cosT  = (const float*)d_in[1];
    const float* sinT  = (const float*)d_in[2];
    const float* Wqkv  = (const float*)d_in[3];
    const float* bqkv  = (const float*)d_in[4];
    const float* Wproj = (const float*)d_in[5];
    const float* bproj = (const float*)d_in[6];

    float* out  = (float*)d_out;                 // (B,S,E)
    float* kout = out + HEAD_ELEMS;              // (B,H,S,D)
    float* vout = out + 2 * HEAD_ELEMS;          // (B,H,S,D)

    __half *xf, *wqf, *wpf, *yf, *qfp, *kfp, *vfp;
    cudaGetSymbolAddress((void**)&xf,  g_xf);
    cudaGetSymbolAddress((void**)&wqf, g_wqkvf);
    cudaGetSymbolAddress((void**)&wpf, g_wprojf);
    cudaGetSymbolAddress((void**)&yf,  g_yf);
    cudaGetSymbolAddress((void**)&qfp, g_qf);
    cudaGetSymbolAddress((void**)&kfp, g_kf);
    cudaGetSymbolAddress((void**)&vfp, g_vf);

    // 0) conversions: x -> fp16, weights -> transposed fp16
    {
        const int n4 = (Mm * Ee) / 4;
        conv_half<<<(n4 + 255) / 256, 256>>>((const float4*)x, (__half2*)xf, n4);
        transpose_half<<<dim3(N_QKV / 32, Ee / 32), 256>>>(Wqkv, wqf, Ee, N_QKV);
        transpose_half<<<dim3(Ee / 32, Ee / 32), 256>>>(Wproj, wpf, Ee, Ee);
    }

    // 1) QKV GEMM (fp16 single-pass, BK=64) + bias + RoPE
    {
        cudaFuncSetAttribute(gemm_mma<1>, cudaFuncAttributeMaxDynamicSharedMemorySize, GEMM_SMEM);
        dim3 grid(N_QKV / 128, Mm / 128);
        gemm_mma<1><<<grid, 128, GEMM_SMEM>>>(xf, wqf, bqkv, cosT, sinT,
                                              nullptr, kout, vout,
                                              qfp, kfp, vfp, Ee, N_QKV);
    }

    // 2) Flash attention: QK fp16 1-pass, PV fp16 1-pass -> fp16 y
    {
        cudaFuncSetAttribute(mha_attn_mma, cudaFuncAttributeMaxDynamicSharedMemorySize, AT_SMEM);
        dim3 grid(Ss / 128, Hh, Bb);
        mha_attn_mma<<<grid, 256, AT_SMEM>>>(qfp, kfp, vfp, yf);
    }

    // 3) Projection GEMM (fp16 single-pass, BK=64) + bias
    {
        cudaFuncSetAttribute(gemm_mma<0>, cudaFuncAttributeMaxDynamicSharedMemorySize, GEMM_SMEM);
        dim3 grid(Ee / 128, Mm / 128);
        gemm_mma<0><<<grid, 128, GEMM_SMEM>>>(yf, wpf, bproj, nullptr, nullptr,
                                              out, nullptr, nullptr,
                                              nullptr, nullptr, nullptr, Ee, Ee);
    }
}

// round 17
// speedup vs baseline: 2.5422x; 1.0110x over previous
#include <cuda_runtime.h>
#include <cuda_bf16.h>
#include <cuda_fp16.h>
#include <cstdint>

// Problem constants
#define Bb 4
#define Ss 2048
#define Ee 2048
#define Hh 16
#define Dd 128
#define Mm (Bb * Ss)          // 8192
#define N_QKV (3 * Ee)        // 6144
#define HEAD_ELEMS ((size_t)Bb * Hh * Ss * Dd)   // 16,777,216

// ---------------------------------------------------------------------------
// Scratch (device globals; no allocation allowed)
// ---------------------------------------------------------------------------
__device__ __half g_qf[HEAD_ELEMS];                              // q fp16 (B,H,S,D), pre-scaled
__device__ __half g_kf[HEAD_ELEMS];                              // k fp16
__device__ __half g_vf[HEAD_ELEMS];                              // v fp16
__device__ __half g_xf[(size_t)Mm * Ee];                         // x fp16
__device__ __half g_wqkvf[(size_t)N_QKV * Ee];                   // Wqkv^T fp16 [N,K]
__device__ __half g_wprojf[(size_t)Ee * Ee];                     // Wproj^T fp16 [N,K]
__device__ __half g_yf[(size_t)Mm * Ee];                         // attn out fp16 (B,S,E)

// ---------------------------------------------------------------------------
// PTX helpers (sm_80-era: mma.sync / ldmatrix / cp.async — legal on sm_103 base)
// ---------------------------------------------------------------------------
__device__ __forceinline__ uint32_t smem_u32(const void* p) {
    uint32_t a;
    asm("{ .reg .u64 t; cvta.to.shared.u64 t, %1; cvt.u32.u64 %0, t; }" : "=r"(a) : "l"(p));
    return a;
}

#define LDM4(r, addr)                                                          \
    asm volatile("ldmatrix.sync.aligned.m8n8.x4.shared.b16 {%0,%1,%2,%3}, [%4];" \
                 : "=r"((r)[0]), "=r"((r)[1]), "=r"((r)[2]), "=r"((r)[3])      \
                 : "r"(addr))

#define LDM4T(r, addr)                                                         \
    asm volatile("ldmatrix.sync.aligned.m8n8.x4.trans.shared.b16 {%0,%1,%2,%3}, [%4];" \
                 : "=r"((r)[0]), "=r"((r)[1]), "=r"((r)[2]), "=r"((r)[3])      \
                 : "r"(addr))

#define MMA_F16(d, a, b0, b1)                                                  \
    asm volatile("mma.sync.aligned.m16n8k16.row.col.f32.f16.f16.f32 "          \
                 "{%0,%1,%2,%3}, {%4,%5,%6,%7}, {%8,%9}, {%0,%1,%2,%3};"       \
                 : "+f"((d)[0]), "+f"((d)[1]), "+f"((d)[2]), "+f"((d)[3])      \
                 : "r"((a)[0]), "r"((a)[1]), "r"((a)[2]), "r"((a)[3]),         \
                   "r"(b0), "r"(b1))

#define CPA16(dst, src)                                                        \
    asm volatile("cp.async.cg.shared.global [%0], [%1], 16;"                   \
                 :: "r"(dst), "l"(src) : "memory")
#define CPA_COMMIT() asm volatile("cp.async.commit_group;" ::: "memory")
#define CPA_WAIT0()  asm volatile("cp.async.wait_group 0;" ::: "memory")
#define CPA_WAIT1()  asm volatile("cp.async.wait_group 1;" ::: "memory")

// pack two fp32 -> fp16x2
__device__ __forceinline__ uint32_t pack_h2(float lo, float hi) {
    __half2 h = __floats2half2_rn(lo, hi);
    return *(uint32_t*)&h;
}

// ---------------------------------------------------------------------------
// Conversion kernels
// ---------------------------------------------------------------------------
__global__ void __launch_bounds__(256)
conv_half(const float4* __restrict__ in, __half2* __restrict__ o, int n4)
{
    int i = blockIdx.x * 256 + threadIdx.x;
    if (i >= n4) return;
    float4 v = in[i];
    o[2 * i]     = __floats2half2_rn(v.x, v.y);
    o[2 * i + 1] = __floats2half2_rn(v.z, v.w);
}

// W [K,N] fp32 -> out [N,K] fp16
__global__ void __launch_bounds__(256)
transpose_half(const float* __restrict__ W, __half* __restrict__ th, int K, int N)
{
    __shared__ float tile[32][33];
    const int n0 = blockIdx.x * 32, k0 = blockIdx.y * 32;
    const int tx = threadIdx.x & 31, ty = threadIdx.x >> 5;
#pragma unroll
    for (int r = ty; r < 32; r += 8)
        tile[r][tx] = W[(size_t)(k0 + r) * N + n0 + tx];
    __syncthreads();
#pragma unroll
    for (int r = ty; r < 32; r += 8)
        th[(size_t)(n0 + r) * K + k0 + tx] = __float2half_rn(tile[tx][r]);
}

// ---------------------------------------------------------------------------
// mma.sync fp16 single-pass GEMM: C[M,N] = A[M,K] * B^T (B stored [N,K]),
// fp32 accum. CTA tile 128x128, 4 warps (2x2), warp tile 64x64, K chunks
// of 32, THREE-stage cp.async pipeline (60KB smem -> 2 CTAs/SM): each
// chunk's load gets two full compute phases to complete (wait_group 1).
// MODE 0: out0 = C + bias (proj).
// MODE 1: QKV epilogue — bias, RoPE, q*scale -> fp16; k,v -> fp32 + fp16.
// ---------------------------------------------------------------------------
#define PITCH 80                       // bytes per 32-elem fp16 row (64B + 16B pad)
#define MAT_BYTES (128 * PITCH)        // 10240
#define STAGE_BYTES (2 * MAT_BYTES)    // A, B = 20480
#define GEMM_SMEM (3 * STAGE_BYTES)    // 61440

template <int MODE>
__global__ void __launch_bounds__(128, 2)
gemm_mma(const __half* __restrict__ Ag, const __half* __restrict__ Bg,
         const float* __restrict__ bias,
         const float* __restrict__ cosT, const float* __restrict__ sinT,
         float* __restrict__ out0, float* __restrict__ out1, float* __restrict__ out2,
         __half* __restrict__ qfp, __half* __restrict__ kfp, __half* __restrict__ vfp,
         int K, int N)
{
    extern __shared__ char sm[];
    const uint32_t sb = smem_u32(sm);
    const int t    = threadIdx.x;
    const int lane = t & 31;
    const int wid  = t >> 5;                 // 0..3
    const int m0   = blockIdx.y * 128;
    const int n0   = blockIdx.x * 128;
    const int m_warp = (wid & 1) * 64;
    const int n_warp = (wid >> 1) * 64;

    float acc[4][8][4];
#pragma unroll
    for (int i = 0; i < 4; i++)
#pragma unroll
        for (int j = 0; j < 8; j++)
#pragma unroll
            for (int k = 0; k < 4; k++) acc[i][j][k] = 0.f;

    const int NCHUNK = K / 32;

    // each matrix: 128 rows x 4 quads = 512 quads; 128 threads -> 4 per thread
    auto load_chunk = [&](int c, int s) {
        const uint32_t stg = sb + s * STAGE_BYTES;
        const int k0 = c * 32;
        const __half* gp[2] = { Ag + (size_t)m0 * K + k0, Bg + (size_t)n0 * K + k0 };
#pragma unroll
        for (int mmat = 0; mmat < 2; mmat++) {
            const uint32_t mb = stg + mmat * MAT_BYTES;
#pragma unroll
            for (int j = 0; j < 4; j++) {
                const int q = t + j * 128;
                const int r = q >> 2, cq = q & 3;
                CPA16(mb + r * PITCH + cq * 16, gp[mmat] + (size_t)r * K + cq * 8);
            }
        }
    };

    const uint32_t a_row  = m_warp + (lane & 15);
    const uint32_t a_byte = ((lane >> 4) & 1) * 16;
    const uint32_t b_row  = n_warp + ((lane >> 4) & 1) * 8 + (lane & 7);
    const uint32_t b_byte = ((lane >> 3) & 1) * 16;

    // prologue: fill stages 0 and 1
    load_chunk(0, 0);
    CPA_COMMIT();
    load_chunk(1, 1);
    CPA_COMMIT();
    CPA_WAIT1();              // stage 0 ready
    __syncthreads();

    for (int c = 0; c < NCHUNK; c++) {
        const int s = c % 3;
        if (c + 2 < NCHUNK) { load_chunk(c + 2, (c + 2) % 3); CPA_COMMIT(); }

        const uint32_t stg = sb + s * STAGE_BYTES;
        const uint32_t Am = stg, Bm = stg + MAT_BYTES;

#pragma unroll
        for (int ks = 0; ks < 2; ks++) {
            const uint32_t koff = ks * 32;
            uint32_t af[4][4];
#pragma unroll
            for (int mt = 0; mt < 4; mt++)
                LDM4(af[mt], Am + (a_row + mt * 16) * PITCH + koff + a_byte);
#pragma unroll
            for (int p = 0; p < 4; p++) {
                uint32_t bf[4];
                LDM4(bf, Bm + (b_row + p * 16) * PITCH + koff + b_byte);
#pragma unroll
                for (int mt = 0; mt < 4; mt++) {
                    MMA_F16(acc[mt][2 * p],     af[mt], bf[0], bf[1]);
                    MMA_F16(acc[mt][2 * p + 1], af[mt], bf[2], bf[3]);
                }
            }
        }
        if (c + 2 < NCHUNK) CPA_WAIT1(); else CPA_WAIT0();
        __syncthreads();
    }

    // ---- epilogue ----
    const int lr = lane >> 2;
    const int lc = (lane & 3) * 2;
    const float rscale = 0.08838834764831845f;   // 1/sqrt(128)

#pragma unroll
    for (int mt = 0; mt < 4; mt++) {
#pragma unroll
        for (int nt = 0; nt < 8; nt++) {
            const int ncol = n_warp + nt * 8 + lc;
            const float b0 = bias[n0 + ncol];
            const float b1 = bias[n0 + ncol + 1];
#pragma unroll
            for (int half = 0; half < 2; half++) {
                const int m = m0 + m_warp + mt * 16 + lr + half * 8;
                float v0 = acc[mt][nt][half * 2 + 0] + b0;
                float v1 = acc[mt][nt][half * 2 + 1] + b1;
                if (MODE == 0) {
                    *(float2*)&out0[(size_t)m * N + n0 + ncol] = make_float2(v0, v1);
                } else {
                    const int part = n0 >> 11;           // 0=q, 1=k, 2=v
                    const int hh   = (n0 & 2047) >> 7;
                    const int bb   = m >> 11;
                    const int ss   = m & 2047;
                    if (part < 2) {
                        const float cs0 = cosT[ss * Dd + ncol];
                        const float sn0 = sinT[ss * Dd + ncol];
                        const float cs1 = cosT[ss * Dd + ncol + 1];
                        const float sn1 = sinT[ss * Dd + ncol + 1];
                        const float e = v0, o = v1;
                        v0 = e * cs0 - o * sn0;
                        v1 = o * cs1 + e * sn1;
                    }
                    size_t idx = ((((size_t)bb * Hh + hh) * Ss) + ss) * Dd + ncol;
                    if (part == 0) {
                        *(uint32_t*)(qfp + idx) = pack_h2(v0 * rscale, v1 * rscale);
                    } else if (part == 1) {
                        *(float2*)&out1[idx] = make_float2(v0, v1);
                        *(uint32_t*)(kfp + idx) = pack_h2(v0, v1);
                    } else {
                        *(float2*)&out2[idx] = make_float2(v0, v1);
                        *(uint32_t*)(vfp + idx) = pack_h2(v0, v1);
                    }
                }
            }
        }
    }
}

// ---------------------------------------------------------------------------
// Tensor-core flash attention, all-fp16 operands (fp32 accum + softmax):
// QK^T fp16 single-pass, P·V fp16 single-pass.
// CTA = 128 q-rows of one (b,h); 8 warps x 16 rows; BK=64; D=128.
// K + V fp16 double-buffered via cp.async; V via ldmatrix.trans.
// ---------------------------------------------------------------------------
#define AT_PITCH 272                 // 128 elems = 256B + 16B pad
#define AT_QBYTES (128 * AT_PITCH)   // 34816
#define AT_KBYTES (64 * AT_PITCH)    // 17408
#define AT_STAGE  (2 * AT_KBYTES)    // Kf, Vf = 34816
#define AT_SMEM   (AT_QBYTES + 2 * AT_STAGE)   // 104448

__global__ void __launch_bounds__(256, 1)
mha_attn_mma(const __half* __restrict__ qf, const __half* __restrict__ kf,
             const __half* __restrict__ vf,
             __half* __restrict__ yf)
{
    extern __shared__ char sm[];
    const uint32_t sb = smem_u32(sm);
    const int t = threadIdx.x, lane = t & 31, w = t >> 5;
    const int q0 = blockIdx.x * 128;
    const int h  = blockIdx.y, b = blockIdx.z;
    const size_t base = ((size_t)b * Hh + h) * (size_t)Ss * Dd;

    const uint32_t QF = sb;
    const uint32_t ST0 = sb + AT_QBYTES;

    // ---- load Q fp16 (128 rows x 256B) ----
    {
        const __half* sq = qf + base + (size_t)q0 * Dd;
#pragma unroll
        for (int j = 0; j < 8; j++) {
            int idx = t + j * 256;               // 2048 16B-chunks
            int r = idx >> 4, c = idx & 15;
            CPA16(QF + r * AT_PITCH + c * 16, sq + (size_t)r * Dd + c * 8);
        }
    }

    auto load_kv = [&](int kt, int s) {
        const size_t off = base + (size_t)kt * 64 * Dd;
        const uint32_t stb = ST0 + s * AT_STAGE;
        const __half* srcs[2] = { kf + off, vf + off };
#pragma unroll
        for (int mmat = 0; mmat < 2; mmat++)
#pragma unroll
            for (int j = 0; j < 4; j++) {
                int idx = t + j * 256;               // 1024 chunks per matrix
                int r = idx >> 4, c = idx & 15;
                CPA16(stb + mmat * AT_KBYTES + r * AT_PITCH + c * 16,
                      srcs[mmat] + (size_t)r * Dd + c * 8);
            }
    };

    load_kv(0, 0);
    CPA_COMMIT();
    CPA_WAIT0();
    __syncthreads();

    const int lr = lane >> 2, lcq = lane & 3;
    // ldmatrix address components
    const uint32_t qrow_off = (uint32_t)(w * 16 + (lane & 15)) * AT_PITCH + ((lane >> 4) & 1) * 16;
    const uint32_t krow_off = (uint32_t)(((lane >> 4) & 1) * 8 + (lane & 7)) * AT_PITCH + ((lane >> 3) & 1) * 16;
    const uint32_t vrow_off = (uint32_t)(lane & 15) * AT_PITCH + ((lane >> 4) & 1) * 16;

    float o[16][4];
#pragma unroll
    for (int i = 0; i < 16; i++)
#pragma unroll
        for (int j = 0; j < 4; j++) o[i][j] = 0.f;
    float mrow[2] = { -1e30f, -1e30f };
    float lrow[2] = { 0.f, 0.f };

    for (int kt = 0; kt < Ss / 64; kt++) {
        const int s = kt & 1;
        if (kt + 1 < Ss / 64) { load_kv(kt + 1, s ^ 1); CPA_COMMIT(); }

        const uint32_t KFs = ST0 + s * AT_STAGE;
        const uint32_t VFs = KFs + AT_KBYTES;

        // ---- S = Q K^T (fp16 single-pass), warp tile 16x64 ----
        float sc[8][4];
#pragma unroll
        for (int i = 0; i < 8; i++)
#pragma unroll
            for (int j = 0; j < 4; j++) sc[i][j] = 0.f;

#pragma unroll
        for (int ks = 0; ks < 8; ks++) {
            uint32_t aqf[4];
            LDM4(aqf, QF + qrow_off + ks * 32);
#pragma unroll
            for (int ntp = 0; ntp < 4; ntp++) {
                uint32_t bkf[4];
                LDM4(bkf, KFs + ntp * 16 * AT_PITCH + krow_off + ks * 32);
                MMA_F16(sc[2 * ntp],     aqf, bkf[0], bkf[1]);
                MMA_F16(sc[2 * ntp + 1], aqf, bkf[2], bkf[3]);
            }
        }

        // ---- online softmax (rows lr and lr+8; quad-local reductions) ----
#pragma unroll
        for (int r = 0; r < 2; r++) {
            float mx = -1e30f;
#pragma unroll
            for (int nt = 0; nt < 8; nt++)
                mx = fmaxf(mx, fmaxf(sc[nt][2 * r], sc[nt][2 * r + 1]));
            mx = fmaxf(mx, __shfl_xor_sync(0xffffffffu, mx, 1));
            mx = fmaxf(mx, __shfl_xor_sync(0xffffffffu, mx, 2));
            const float mn = fmaxf(mrow[r], mx);
            const float al = __expf(mrow[r] - mn);
            mrow[r] = mn;
            float rs = 0.f;
#pragma unroll
            for (int nt = 0; nt < 8; nt++) {
                float p0 = __expf(sc[nt][2 * r]     - mn);
                float p1 = __expf(sc[nt][2 * r + 1] - mn);
                sc[nt][2 * r] = p0; sc[nt][2 * r + 1] = p1;
                rs += p0 + p1;
            }
            rs += __shfl_xor_sync(0xffffffffu, rs, 1);
            rs += __shfl_xor_sync(0xffffffffu, rs, 2);
            lrow[r] = lrow[r] * al + rs;
#pragma unroll
            for (int nt = 0; nt < 16; nt++) {
                o[nt][2 * r] *= al; o[nt][2 * r + 1] *= al;
            }
        }

        // ---- O += P V (fp16 single-pass); P A-frags straight from sc regs ----
#pragma unroll
        for (int kg = 0; kg < 4; kg++) {
            uint32_t af[4];
#pragma unroll
            for (int u = 0; u < 2; u++) {          // u=0: ntile 2kg, u=1: ntile 2kg+1
                af[2 * u]     = pack_h2(sc[2 * kg + u][0], sc[2 * kg + u][1]);
                af[2 * u + 1] = pack_h2(sc[2 * kg + u][2], sc[2 * kg + u][3]);
            }
#pragma unroll
            for (int dg = 0; dg < 8; dg++) {
                uint32_t bv[4];
                LDM4T(bv, VFs + kg * 16 * AT_PITCH + vrow_off + dg * 32);
                MMA_F16(o[2 * dg],     af, bv[0], bv[1]);
                MMA_F16(o[2 * dg + 1], af, bv[2], bv[3]);
            }
        }

        CPA_WAIT0();
        __syncthreads();
    }

    // ---- epilogue: scale by 1/l, emit fp16 y in (B,S,E) ----
    const float inv0 = 1.f / lrow[0];
    const float inv1 = 1.f / lrow[1];
    const int row0 = q0 + w * 16 + lr;
    const int row1 = row0 + 8;
#pragma unroll
    for (int nt = 0; nt < 16; nt++) {
        const int col = h * Dd + nt * 8 + 2 * lcq;
        {
            size_t idx = ((size_t)b * Ss + row0) * Ee + col;
            *(__half2*)(yf + idx) = __floats2half2_rn(o[nt][0] * inv0, o[nt][1] * inv0);
        }
        {
            size_t idx = ((size_t)b * Ss + row1) * Ee + col;
            *(__half2*)(yf + idx) = __floats2half2_rn(o[nt][2] * inv1, o[nt][3] * inv1);
        }
    }
}

// ---------------------------------------------------------------------------
extern "C" void kernel_launch(void* const* d_in, const int* in_sizes, int n_in,
                              void* d_out, int out_size)
{
    const float* x     = (const float*)d_in[0];
    const float* cosT  = (const float*)d_in[1];
    const float* sinT  = (const float*)d_in[2];
    const float* Wqkv  = (const float*)d_in[3];
    const float* bqkv  = (const float*)d_in[4];
    const float* Wproj = (const float*)d_in[5];
    const float* bproj = (const float*)d_in[6];

    float* out  = (float*)d_out;                 // (B,S,E)
    float* kout = out + HEAD_ELEMS;              // (B,H,S,D)
    float* vout = out + 2 * HEAD_ELEMS;          // (B,H,S,D)

    __half *xf, *wqf, *wpf, *yf, *qfp, *kfp, *vfp;
    cudaGetSymbolAddress((void**)&xf,  g_xf);
    cudaGetSymbolAddress((void**)&wqf, g_wqkvf);
    cudaGetSymbolAddress((void**)&wpf, g_wprojf);
    cudaGetSymbolAddress((void**)&yf,  g_yf);
    cudaGetSymbolAddress((void**)&qfp, g_qf);
    cudaGetSymbolAddress((void**)&kfp, g_kf);
    cudaGetSymbolAddress((void**)&vfp, g_vf);

    // 0) conversions: x -> fp16, weights -> transposed fp16
    {
        const int n4 = (Mm * Ee) / 4;
        conv_half<<<(n4 + 255) / 256, 256>>>((const float4*)x, (__half2*)xf, n4);
        transpose_half<<<dim3(N_QKV / 32, Ee / 32), 256>>>(Wqkv, wqf, Ee, N_QKV);
        transpose_half<<<dim3(Ee / 32, Ee / 32), 256>>>(Wproj, wpf, Ee, Ee);
    }

    // 1) QKV GEMM (fp16 single-pass, 3-stage pipeline) + bias + RoPE
    {
        cudaFuncSetAttribute(gemm_mma<1>, cudaFuncAttributeMaxDynamicSharedMemorySize, GEMM_SMEM);
        dim3 grid(N_QKV / 128, Mm / 128);
        gemm_mma<1><<<grid, 128, GEMM_SMEM>>>(xf, wqf, bqkv, cosT, sinT,
                                              nullptr, kout, vout,
                                              qfp, kfp, vfp, Ee, N_QKV);
    }

    // 2) Flash attention: QK fp16 1-pass, PV fp16 1-pass -> fp16 y
    {
        cudaFuncSetAttribute(mha_attn_mma, cudaFuncAttributeMaxDynamicSharedMemorySize, AT_SMEM);
        dim3 grid(Ss / 128, Hh, Bb);
        mha_attn_mma<<<grid, 256, AT_SMEM>>>(qfp, kfp, vfp, yf);
    }

    // 3) Projection GEMM (fp16 single-pass, 3-stage pipeline) + bias
    {
        cudaFuncSetAttribute(gemm_mma<0>, cudaFuncAttributeMaxDynamicSharedMemorySize, GEMM_SMEM);
        dim3 grid(Ee / 128, Mm / 128);
        gemm_mma<0><<<grid, 128, GEMM_SMEM>>>(yf, wpf, bproj, nullptr, nullptr,
                                              out, nullptr, nullptr,
                                              nullptr, nullptr, nullptr, Ee, Ee);
    }
}